// round 6
// baseline (speedup 1.0000x reference)
#include <cuda_runtime.h>
#include <cstdint>

#define N_NODES 100000
#define NNZ     1600000
#define IN_CH   256
#define OUT_CH  64

// ---------------------------------------------------------------------------
// Device scratch (no allocations allowed)
// ---------------------------------------------------------------------------
__device__ float g_Xp[(size_t)N_NODES * OUT_CH];   // 25.6 MB projected features
__device__ float g_WT[IN_CH * OUT_CH];             // 64 KB transposed weight
__device__ int   g_idx_is32;                       // 1 if indices are int32

__device__ int   g_count[N_NODES];                 // per-row nnz counts
__device__ int   g_rowptr[N_NODES + 1];            // CSR row pointers
__device__ int   g_cursor[N_NODES];                // scatter cursors
__device__ int2  g_pairs[NNZ];                     // sorted {col, val-bits}, 12.8 MB

// ---------------------------------------------------------------------------
// Detect whether L_rows/L_cols are int32 or int64 (jax x64 flag ambiguity).
// int64 nonneg < 2^31 => every odd 32-bit word is 0. Deterministic.
// ---------------------------------------------------------------------------
__global__ void detect_idx_kernel(const unsigned int* __restrict__ rows_u32) {
    __shared__ int s_any;
    if (threadIdx.x == 0) s_any = 0;
    __syncthreads();
    int local = 0;
    for (int i = threadIdx.x; i < 1024; i += blockDim.x) {
        if (rows_u32[2 * i + 1] != 0u) local = 1;
    }
    if (local) atomicOr(&s_any, 1);
    __syncthreads();
    if (threadIdx.x == 0) g_idx_is32 = s_any;
}

// ---------------------------------------------------------------------------
// Zero the per-row counters (must happen every launch — graph replays).
// ---------------------------------------------------------------------------
__global__ void zero_counts_kernel() {
    int i = blockIdx.x * blockDim.x + threadIdx.x;
    if (i < N_NODES) g_count[i] = 0;
}

__device__ __forceinline__ int load_idx(const void* p, int e) {
    if (g_idx_is32)
        return __ldg(reinterpret_cast<const int*>(p) + e);
    return (int)__ldg(reinterpret_cast<const long long*>(p) + e);
}

// ---------------------------------------------------------------------------
// Pass 1: histogram of row indices.
// ---------------------------------------------------------------------------
__global__ void __launch_bounds__(256) count_kernel(const void* __restrict__ rows_p) {
    int e = blockIdx.x * 256 + threadIdx.x;
    if (e >= NNZ) return;
    atomicAdd(&g_count[load_idx(rows_p, e)], 1);
}

// ---------------------------------------------------------------------------
// Pass 2: exclusive prefix sum over 100000 counts. Single block, 1024 thr,
// each thread owns a contiguous chunk of 98 elements.
// ---------------------------------------------------------------------------
__global__ void __launch_bounds__(1024) scan_kernel() {
    __shared__ int part[1024];
    const int t = threadIdx.x;
    const int CH = 98;                       // 1024*98 >= 100000
    int base = t * CH;
    int s = 0;
    for (int i = 0; i < CH; i++) {
        int j = base + i;
        if (j < N_NODES) s += g_count[j];
    }
    part[t] = s;
    __syncthreads();
    for (int off = 1; off < 1024; off <<= 1) {
        int v = (t >= off) ? part[t - off] : 0;
        __syncthreads();
        part[t] += v;
        __syncthreads();
    }
    int run = part[t] - s;                   // exclusive prefix of this chunk
    for (int i = 0; i < CH; i++) {
        int j = base + i;
        if (j < N_NODES) {
            g_rowptr[j] = run;
            g_cursor[j] = run;
            run += g_count[j];
        }
    }
    if (t == 1023) g_rowptr[N_NODES] = run;  // == NNZ
}

// ---------------------------------------------------------------------------
// Pass 3: scatter edges into row-sorted order as {col, val} pairs.
// ---------------------------------------------------------------------------
__global__ void __launch_bounds__(256) scatter_kernel(
    const void* __restrict__ rows_p,
    const void* __restrict__ cols_p,
    const float* __restrict__ vals)
{
    int e = blockIdx.x * 256 + threadIdx.x;
    if (e >= NNZ) return;
    int row = load_idx(rows_p, e);
    int col = load_idx(cols_p, e);
    float v = __ldg(vals + e);
    int pos = atomicAdd(&g_cursor[row], 1);
    g_pairs[pos] = make_int2(col, __float_as_int(v));
}

// ---------------------------------------------------------------------------
// Transpose W [OUT_CH, IN_CH] -> WT [IN_CH, OUT_CH]
// ---------------------------------------------------------------------------
__global__ void transpose_w_kernel(const float* __restrict__ W) {
    int idx = blockIdx.x * blockDim.x + threadIdx.x;   // 0 .. 16383
    if (idx < IN_CH * OUT_CH) {
        int o = idx & (OUT_CH - 1);
        int k = idx >> 6;
        g_WT[k * OUT_CH + o] = W[o * IN_CH + k];
    }
}

// ---------------------------------------------------------------------------
// GEMM: Xp = X @ W^T with packed f32x2 FMAs (FFMA2).
// CTA = 128 rows x 64 outputs, k-chunked by 32, 256 threads.
// Thread (p = tid&15, q = tid>>4):
//   rows  {4p..4p+3} and {64+4p..64+4p+3}  (4 f32x2 row-pairs)
//   outs  {4q..4q+3}                        (4 duplicated f32x2)
//   16 fma.rn.f32x2 per k = 32 FMA per k per thread.
// ---------------------------------------------------------------------------
__device__ __forceinline__ uint32_t smem_u32(const void* p) {
    uint32_t a;
    asm("{ .reg .u64 t; cvta.to.shared.u64 t, %1; cvt.u32.u64 %0, t; }"
        : "=r"(a) : "l"(p));
    return a;
}

#define FMA2(acc, x, w) \
    asm("fma.rn.f32x2 %0, %1, %2, %0;" : "+l"(acc) : "l"(x), "l"(w))

__global__ void __launch_bounds__(256) gemm_kernel(const float* __restrict__ X) {
    __shared__ float  Xs[32 * 128];    // [k][row], 16 KB
    __shared__ float2 Wsd[32 * 64];    // [k][o] dup pairs, 16 KB

    const int tid = threadIdx.x;
    const int p = tid & 15;
    const int q = tid >> 4;
    const int row0 = blockIdx.x * 128;

    unsigned long long acc[4][4];
#pragma unroll
    for (int i = 0; i < 4; i++)
#pragma unroll
        for (int j = 0; j < 4; j++) acc[i][j] = 0ull;

    const uint32_t xs_base = smem_u32(Xs) + p * 16;
    const uint32_t ws_base = smem_u32(Wsd) + q * 32;

    for (int kc = 0; kc < IN_CH; kc += 32) {
        // fill X tile transposed: Xs[k][r] = X[row0+r][kc+k]
#pragma unroll
        for (int i = 0; i < 4; i++) {
            int fidx = tid + i * 256;      // 0..1023
            int r  = fidx & 127;
            int kq = fidx >> 7;            // 0..7
            int grow = row0 + r;
            if (grow >= N_NODES) grow = N_NODES - 1;   // clamp (dup, harmless)
            float4 v = *reinterpret_cast<const float4*>(
                X + (size_t)grow * IN_CH + kc + kq * 4);
            Xs[(kq * 4 + 0) * 128 + r] = v.x;
            Xs[(kq * 4 + 1) * 128 + r] = v.y;
            Xs[(kq * 4 + 2) * 128 + r] = v.z;
            Xs[(kq * 4 + 3) * 128 + r] = v.w;
        }
        // fill W tile duplicated: Wsd[k][o] = {w, w}
#pragma unroll
        for (int i = 0; i < 8; i++) {
            int idx = tid + i * 256;       // 0..2047
            int k = idx >> 6;
            int o = idx & 63;
            float w = g_WT[(kc + k) * OUT_CH + o];
            Wsd[k * 64 + o] = make_float2(w, w);
        }
        __syncthreads();

#pragma unroll 4
        for (int k = 0; k < 32; k++) {
            uint32_t xa = xs_base + k * 512;
            uint32_t wa = ws_base + k * 512;
            unsigned long long x0, x1, x2, x3, w0, w1, w2, w3;
            asm volatile("ld.shared.v2.u64 {%0,%1}, [%2];"
                         : "=l"(x0), "=l"(x1) : "r"(xa));
            asm volatile("ld.shared.v2.u64 {%0,%1}, [%2];"
                         : "=l"(x2), "=l"(x3) : "r"(xa + 256));
            asm volatile("ld.shared.v2.u64 {%0,%1}, [%2];"
                         : "=l"(w0), "=l"(w1) : "r"(wa));
            asm volatile("ld.shared.v2.u64 {%0,%1}, [%2];"
                         : "=l"(w2), "=l"(w3) : "r"(wa + 16));
            FMA2(acc[0][0], x0, w0); FMA2(acc[0][1], x0, w1);
            FMA2(acc[0][2], x0, w2); FMA2(acc[0][3], x0, w3);
            FMA2(acc[1][0], x1, w0); FMA2(acc[1][1], x1, w1);
            FMA2(acc[1][2], x1, w2); FMA2(acc[1][3], x1, w3);
            FMA2(acc[2][0], x2, w0); FMA2(acc[2][1], x2, w1);
            FMA2(acc[2][2], x2, w2); FMA2(acc[2][3], x2, w3);
            FMA2(acc[3][0], x3, w0); FMA2(acc[3][1], x3, w1);
            FMA2(acc[3][2], x3, w2); FMA2(acc[3][3], x3, w3);
        }
        __syncthreads();
    }

    // writeback: rows {g*64 + 4p + d}, outputs 4q..4q+3
#pragma unroll
    for (int g = 0; g < 2; g++) {
#pragma unroll
        for (int d = 0; d < 4; d++) {
            int grow = row0 + g * 64 + 4 * p + d;
            if (grow < N_NODES) {
                int pg = g * 2 + (d >> 1);
                int h  = d & 1;
                float2 a0 = *reinterpret_cast<float2*>(&acc[pg][0]);
                float2 a1 = *reinterpret_cast<float2*>(&acc[pg][1]);
                float2 a2 = *reinterpret_cast<float2*>(&acc[pg][2]);
                float2 a3 = *reinterpret_cast<float2*>(&acc[pg][3]);
                float4 outv;
                outv.x = h ? a0.y : a0.x;
                outv.y = h ? a1.y : a1.x;
                outv.z = h ? a2.y : a2.x;
                outv.w = h ? a3.y : a3.x;
                *reinterpret_cast<float4*>(
                    g_Xp + (size_t)grow * OUT_CH + 4 * q) = outv;
            }
        }
    }
}

// ---------------------------------------------------------------------------
// CSR SpMM: one warp per output row, no atomics.
// Lane owns 2 channels (float2). 4-deep software pipeline over edges so
// gathers are independent (col load -> x load chain amortized 4x).
// Every row is written (zeros for empty rows) -> no output pre-zeroing.
// ---------------------------------------------------------------------------
__global__ void __launch_bounds__(256) csr_spmm_kernel(float* __restrict__ out) {
    int w = (blockIdx.x * 256 + threadIdx.x) >> 5;
    if (w >= N_NODES) return;
    int lane = threadIdx.x & 31;

    int s = __ldg(&g_rowptr[w]);
    int e = __ldg(&g_rowptr[w + 1]);

    const float2* Xp2 = reinterpret_cast<const float2*>(g_Xp);
    float2 acc = make_float2(0.f, 0.f);

    int i = s;
    for (; i + 4 <= e; i += 4) {
        int2 p0 = __ldg(&g_pairs[i + 0]);
        int2 p1 = __ldg(&g_pairs[i + 1]);
        int2 p2 = __ldg(&g_pairs[i + 2]);
        int2 p3 = __ldg(&g_pairs[i + 3]);
        float2 x0 = __ldg(Xp2 + (size_t)p0.x * 32 + lane);
        float2 x1 = __ldg(Xp2 + (size_t)p1.x * 32 + lane);
        float2 x2 = __ldg(Xp2 + (size_t)p2.x * 32 + lane);
        float2 x3 = __ldg(Xp2 + (size_t)p3.x * 32 + lane);
        float v0 = __int_as_float(p0.y), v1 = __int_as_float(p1.y);
        float v2 = __int_as_float(p2.y), v3 = __int_as_float(p3.y);
        acc.x += v0 * x0.x; acc.y += v0 * x0.y;
        acc.x += v1 * x1.x; acc.y += v1 * x1.y;
        acc.x += v2 * x2.x; acc.y += v2 * x2.y;
        acc.x += v3 * x3.x; acc.y += v3 * x3.y;
    }
    for (; i < e; i++) {
        int2 pr = __ldg(&g_pairs[i]);
        float2 x = __ldg(Xp2 + (size_t)pr.x * 32 + lane);
        float v = __int_as_float(pr.y);
        acc.x += v * x.x; acc.y += v * x.y;
    }

    reinterpret_cast<float2*>(out)[(size_t)w * 32 + lane] = acc;
}

// ---------------------------------------------------------------------------
// kernel_launch
// Inputs (metadata order): g1, g2, X, W_lin, L_rows, L_cols, L_vals
// ---------------------------------------------------------------------------
extern "C" void kernel_launch(void* const* d_in, const int* in_sizes, int n_in,
                              void* d_out, int out_size) {
    int base = n_in - 5;   // index of X (robust to scalar args being dropped)
    const float* X      = reinterpret_cast<const float*>(d_in[base + 0]);
    const float* W      = reinterpret_cast<const float*>(d_in[base + 1]);
    const void*  L_rows = d_in[base + 2];
    const void*  L_cols = d_in[base + 3];
    const float* L_vals = reinterpret_cast<const float*>(d_in[base + 4]);
    float* out = reinterpret_cast<float*>(d_out);

    const int EB = (NNZ + 255) / 256;            // edge-parallel blocks

    // index dtype detection + CSR build
    detect_idx_kernel<<<1, 256>>>(reinterpret_cast<const unsigned int*>(L_rows));
    zero_counts_kernel<<<(N_NODES + 255) / 256, 256>>>();
    count_kernel<<<EB, 256>>>(L_rows);
    scan_kernel<<<1, 1024>>>();
    scatter_kernel<<<EB, 256>>>(L_rows, L_cols, L_vals);

    // dense projection Xp = X @ W^T (FFMA2)
    transpose_w_kernel<<<(IN_CH * OUT_CH + 255) / 256, 256>>>(W);
    gemm_kernel<<<(N_NODES + 127) / 128, 256>>>(X);

    // atomic-free CSR SpMM (one warp per row)
    csr_spmm_kernel<<<(N_NODES * 32 + 255) / 256, 256>>>(out);
}

// round 8
// speedup vs baseline: 1.7377x; 1.7377x over previous
#include <cuda_runtime.h>
#include <cstdint>

#define N_NODES 100000
#define NNZ     1600000
#define IN_CH   256
#define OUT_CH  64

#define SCAN_CHUNK 256
#define SCAN_NB    ((N_NODES + SCAN_CHUNK - 1) / SCAN_CHUNK)   // 391

// ---------------------------------------------------------------------------
// Device scratch (no allocations allowed)
// ---------------------------------------------------------------------------
__device__ float g_Xp[(size_t)N_NODES * OUT_CH];   // 25.6 MB projected features
__device__ float g_WT[IN_CH * OUT_CH];             // 64 KB transposed weight
__device__ int   g_idx_is32;                       // 1 if indices are int32

__device__ int   g_count[N_NODES];                 // per-row nnz counts
__device__ int   g_rowptr[N_NODES + 1];            // CSR row pointers
__device__ int   g_cursor[N_NODES];                // scatter cursors
__device__ int   g_blocksum[SCAN_NB];              // scan level-1 partials
__device__ int   g_blockoff[SCAN_NB];              // scan level-1 offsets
__device__ int2  g_pairs[NNZ];                     // sorted {col, val-bits}, 12.8 MB

// ---------------------------------------------------------------------------
// Detect whether L_rows/L_cols are int32 or int64 (jax x64 flag ambiguity).
// int64 nonneg < 2^31 => every odd 32-bit word is 0. Deterministic.
// ---------------------------------------------------------------------------
__global__ void detect_idx_kernel(const unsigned int* __restrict__ rows_u32) {
    __shared__ int s_any;
    if (threadIdx.x == 0) s_any = 0;
    __syncthreads();
    int local = 0;
    for (int i = threadIdx.x; i < 1024; i += blockDim.x) {
        if (rows_u32[2 * i + 1] != 0u) local = 1;
    }
    if (local) atomicOr(&s_any, 1);
    __syncthreads();
    if (threadIdx.x == 0) g_idx_is32 = s_any;
}

// ---------------------------------------------------------------------------
// Zero the per-row counters (must happen every launch — graph replays).
// ---------------------------------------------------------------------------
__global__ void zero_counts_kernel() {
    int i = blockIdx.x * blockDim.x + threadIdx.x;
    if (i < N_NODES) g_count[i] = 0;
}

__device__ __forceinline__ int load_idx(const void* p, int e) {
    if (g_idx_is32)
        return __ldg(reinterpret_cast<const int*>(p) + e);
    return (int)__ldg(reinterpret_cast<const long long*>(p) + e);
}

// ---------------------------------------------------------------------------
// Pass 1: histogram of row indices.
// ---------------------------------------------------------------------------
__global__ void __launch_bounds__(256) count_kernel(const void* __restrict__ rows_p) {
    int e = blockIdx.x * 256 + threadIdx.x;
    if (e >= NNZ) return;
    atomicAdd(&g_count[load_idx(rows_p, e)], 1);
}

// ---------------------------------------------------------------------------
// Pass 2a: per-block sum of 256 counts -> g_blocksum  (391 blocks)
// ---------------------------------------------------------------------------
__global__ void __launch_bounds__(256) scan_partial_kernel() {
    __shared__ int sh[256];
    int i = blockIdx.x * SCAN_CHUNK + threadIdx.x;
    sh[threadIdx.x] = (i < N_NODES) ? g_count[i] : 0;
    __syncthreads();
#pragma unroll
    for (int off = 128; off > 0; off >>= 1) {
        if (threadIdx.x < off) sh[threadIdx.x] += sh[threadIdx.x + off];
        __syncthreads();
    }
    if (threadIdx.x == 0) g_blocksum[blockIdx.x] = sh[0];
}

// ---------------------------------------------------------------------------
// Pass 2b: exclusive scan of 391 block sums. One block, 512 threads.
// ---------------------------------------------------------------------------
__global__ void __launch_bounds__(512) scan_blocksums_kernel() {
    __shared__ int sh[512];
    int t = threadIdx.x;
    int v = (t < SCAN_NB) ? g_blocksum[t] : 0;
    sh[t] = v;
    __syncthreads();
#pragma unroll
    for (int off = 1; off < 512; off <<= 1) {
        int u = (t >= off) ? sh[t - off] : 0;
        __syncthreads();
        sh[t] += u;
        __syncthreads();
    }
    if (t < SCAN_NB) g_blockoff[t] = sh[t] - v;   // exclusive
}

// ---------------------------------------------------------------------------
// Pass 2c: exclusive scan within each 256-chunk + block offset -> rowptr/cursor.
// ---------------------------------------------------------------------------
__global__ void __launch_bounds__(256) scan_final_kernel() {
    __shared__ int sh[256];
    int t = threadIdx.x;
    int i = blockIdx.x * SCAN_CHUNK + t;
    int v = (i < N_NODES) ? g_count[i] : 0;
    sh[t] = v;
    __syncthreads();
#pragma unroll
    for (int off = 1; off < 256; off <<= 1) {
        int u = (t >= off) ? sh[t - off] : 0;
        __syncthreads();
        sh[t] += u;
        __syncthreads();
    }
    if (i < N_NODES) {
        int excl = g_blockoff[blockIdx.x] + sh[t] - v;
        g_rowptr[i] = excl;
        g_cursor[i] = excl;
    }
    if (i == 0) g_rowptr[N_NODES] = NNZ;
}

// ---------------------------------------------------------------------------
// Pass 3: scatter edges into row-sorted order as {col, val} pairs.
// ---------------------------------------------------------------------------
__global__ void __launch_bounds__(256) scatter_kernel(
    const void* __restrict__ rows_p,
    const void* __restrict__ cols_p,
    const float* __restrict__ vals)
{
    int e = blockIdx.x * 256 + threadIdx.x;
    if (e >= NNZ) return;
    int row = load_idx(rows_p, e);
    int col = load_idx(cols_p, e);
    float v = __ldg(vals + e);
    int pos = atomicAdd(&g_cursor[row], 1);
    g_pairs[pos] = make_int2(col, __float_as_int(v));
}

// ---------------------------------------------------------------------------
// Transpose W [OUT_CH, IN_CH] -> WT [IN_CH, OUT_CH]
// ---------------------------------------------------------------------------
__global__ void transpose_w_kernel(const float* __restrict__ W) {
    int idx = blockIdx.x * blockDim.x + threadIdx.x;   // 0 .. 16383
    if (idx < IN_CH * OUT_CH) {
        int o = idx & (OUT_CH - 1);
        int k = idx >> 6;
        g_WT[k * OUT_CH + o] = W[o * IN_CH + k];
    }
}

// ---------------------------------------------------------------------------
// GEMM: Xp = X @ W^T with packed f32x2 FMAs (FFMA2).
// CTA = 128 rows x 64 outputs, k-chunked by 32, 256 threads.
// Thread (p = tid&15, q = tid>>4):
//   rows  {4p..4p+3} and {64+4p..64+4p+3}  (4 f32x2 row-pairs)
//   outs  {4q..4q+3}                        (4 duplicated f32x2)
//   16 fma.rn.f32x2 per k = 32 FMA per k per thread.
// ---------------------------------------------------------------------------
__device__ __forceinline__ uint32_t smem_u32(const void* p) {
    uint32_t a;
    asm("{ .reg .u64 t; cvta.to.shared.u64 t, %1; cvt.u32.u64 %0, t; }"
        : "=r"(a) : "l"(p));
    return a;
}

#define FMA2(acc, x, w) \
    asm("fma.rn.f32x2 %0, %1, %2, %0;" : "+l"(acc) : "l"(x), "l"(w))

__global__ void __launch_bounds__(256) gemm_kernel(const float* __restrict__ X) {
    __shared__ float  Xs[32 * 128];    // [k][row], 16 KB
    __shared__ float2 Wsd[32 * 64];    // [k][o] dup pairs, 16 KB

    const int tid = threadIdx.x;
    const int p = tid & 15;
    const int q = tid >> 4;
    const int row0 = blockIdx.x * 128;

    unsigned long long acc[4][4];
#pragma unroll
    for (int i = 0; i < 4; i++)
#pragma unroll
        for (int j = 0; j < 4; j++) acc[i][j] = 0ull;

    const uint32_t xs_base = smem_u32(Xs) + p * 16;
    const uint32_t ws_base = smem_u32(Wsd) + q * 32;

    for (int kc = 0; kc < IN_CH; kc += 32) {
        // fill X tile transposed: Xs[k][r] = X[row0+r][kc+k]
#pragma unroll
        for (int i = 0; i < 4; i++) {
            int fidx = tid + i * 256;      // 0..1023
            int r  = fidx & 127;
            int kq = fidx >> 7;            // 0..7
            int grow = row0 + r;
            if (grow >= N_NODES) grow = N_NODES - 1;   // clamp (dup, harmless)
            float4 v = *reinterpret_cast<const float4*>(
                X + (size_t)grow * IN_CH + kc + kq * 4);
            Xs[(kq * 4 + 0) * 128 + r] = v.x;
            Xs[(kq * 4 + 1) * 128 + r] = v.y;
            Xs[(kq * 4 + 2) * 128 + r] = v.z;
            Xs[(kq * 4 + 3) * 128 + r] = v.w;
        }
        // fill W tile duplicated: Wsd[k][o] = {w, w}
#pragma unroll
        for (int i = 0; i < 8; i++) {
            int idx = tid + i * 256;       // 0..2047
            int k = idx >> 6;
            int o = idx & 63;
            float w = g_WT[(kc + k) * OUT_CH + o];
            Wsd[k * 64 + o] = make_float2(w, w);
        }
        __syncthreads();

#pragma unroll 4
        for (int k = 0; k < 32; k++) {
            uint32_t xa = xs_base + k * 512;
            uint32_t wa = ws_base + k * 512;
            unsigned long long x0, x1, x2, x3, w0, w1, w2, w3;
            asm volatile("ld.shared.v2.u64 {%0,%1}, [%2];"
                         : "=l"(x0), "=l"(x1) : "r"(xa));
            asm volatile("ld.shared.v2.u64 {%0,%1}, [%2];"
                         : "=l"(x2), "=l"(x3) : "r"(xa + 256));
            asm volatile("ld.shared.v2.u64 {%0,%1}, [%2];"
                         : "=l"(w0), "=l"(w1) : "r"(wa));
            asm volatile("ld.shared.v2.u64 {%0,%1}, [%2];"
                         : "=l"(w2), "=l"(w3) : "r"(wa + 16));
            FMA2(acc[0][0], x0, w0); FMA2(acc[0][1], x0, w1);
            FMA2(acc[0][2], x0, w2); FMA2(acc[0][3], x0, w3);
            FMA2(acc[1][0], x1, w0); FMA2(acc[1][1], x1, w1);
            FMA2(acc[1][2], x1, w2); FMA2(acc[1][3], x1, w3);
            FMA2(acc[2][0], x2, w0); FMA2(acc[2][1], x2, w1);
            FMA2(acc[2][2], x2, w2); FMA2(acc[2][3], x2, w3);
            FMA2(acc[3][0], x3, w0); FMA2(acc[3][1], x3, w1);
            FMA2(acc[3][2], x3, w2); FMA2(acc[3][3], x3, w3);
        }
        __syncthreads();
    }

    // writeback: rows {g*64 + 4p + d}, outputs 4q..4q+3
#pragma unroll
    for (int g = 0; g < 2; g++) {
#pragma unroll
        for (int d = 0; d < 4; d++) {
            int grow = row0 + g * 64 + 4 * p + d;
            if (grow < N_NODES) {
                int pg = g * 2 + (d >> 1);
                int h  = d & 1;
                float2 a0 = *reinterpret_cast<float2*>(&acc[pg][0]);
                float2 a1 = *reinterpret_cast<float2*>(&acc[pg][1]);
                float2 a2 = *reinterpret_cast<float2*>(&acc[pg][2]);
                float2 a3 = *reinterpret_cast<float2*>(&acc[pg][3]);
                float4 outv;
                outv.x = h ? a0.y : a0.x;
                outv.y = h ? a1.y : a1.x;
                outv.z = h ? a2.y : a2.x;
                outv.w = h ? a3.y : a3.x;
                *reinterpret_cast<float4*>(
                    g_Xp + (size_t)grow * OUT_CH + 4 * q) = outv;
            }
        }
    }
}

// ---------------------------------------------------------------------------
// CSR SpMM: one warp per output row, no atomics.
// Lane owns 2 channels (float2). 4-deep software pipeline over edges so
// gathers are independent. Every row is written -> no output pre-zeroing.
// ---------------------------------------------------------------------------
__global__ void __launch_bounds__(256) csr_spmm_kernel(float* __restrict__ out) {
    int w = (blockIdx.x * 256 + threadIdx.x) >> 5;
    if (w >= N_NODES) return;
    int lane = threadIdx.x & 31;

    int s = __ldg(&g_rowptr[w]);
    int e = __ldg(&g_rowptr[w + 1]);

    const float2* Xp2 = reinterpret_cast<const float2*>(g_Xp);
    float2 acc = make_float2(0.f, 0.f);

    int i = s;
    for (; i + 4 <= e; i += 4) {
        int2 p0 = __ldg(&g_pairs[i + 0]);
        int2 p1 = __ldg(&g_pairs[i + 1]);
        int2 p2 = __ldg(&g_pairs[i + 2]);
        int2 p3 = __ldg(&g_pairs[i + 3]);
        float2 x0 = __ldg(Xp2 + (size_t)p0.x * 32 + lane);
        float2 x1 = __ldg(Xp2 + (size_t)p1.x * 32 + lane);
        float2 x2 = __ldg(Xp2 + (size_t)p2.x * 32 + lane);
        float2 x3 = __ldg(Xp2 + (size_t)p3.x * 32 + lane);
        float v0 = __int_as_float(p0.y), v1 = __int_as_float(p1.y);
        float v2 = __int_as_float(p2.y), v3 = __int_as_float(p3.y);
        acc.x += v0 * x0.x; acc.y += v0 * x0.y;
        acc.x += v1 * x1.x; acc.y += v1 * x1.y;
        acc.x += v2 * x2.x; acc.y += v2 * x2.y;
        acc.x += v3 * x3.x; acc.y += v3 * x3.y;
    }
    for (; i < e; i++) {
        int2 pr = __ldg(&g_pairs[i]);
        float2 x = __ldg(Xp2 + (size_t)pr.x * 32 + lane);
        float v = __int_as_float(pr.y);
        acc.x += v * x.x; acc.y += v * x.y;
    }

    reinterpret_cast<float2*>(out)[(size_t)w * 32 + lane] = acc;
}

// ---------------------------------------------------------------------------
// kernel_launch
// Inputs (metadata order): g1, g2, X, W_lin, L_rows, L_cols, L_vals
// ---------------------------------------------------------------------------
extern "C" void kernel_launch(void* const* d_in, const int* in_sizes, int n_in,
                              void* d_out, int out_size) {
    int base = n_in - 5;   // index of X (robust to scalar args being dropped)
    const float* X      = reinterpret_cast<const float*>(d_in[base + 0]);
    const float* W      = reinterpret_cast<const float*>(d_in[base + 1]);
    const void*  L_rows = d_in[base + 2];
    const void*  L_cols = d_in[base + 3];
    const float* L_vals = reinterpret_cast<const float*>(d_in[base + 4]);
    float* out = reinterpret_cast<float*>(d_out);

    const int EB = (NNZ + 255) / 256;            // edge-parallel blocks

    // index dtype detection + CSR build
    detect_idx_kernel<<<1, 256>>>(reinterpret_cast<const unsigned int*>(L_rows));
    zero_counts_kernel<<<(N_NODES + 255) / 256, 256>>>();
    count_kernel<<<EB, 256>>>(L_rows);
    scan_partial_kernel<<<SCAN_NB, 256>>>();
    scan_blocksums_kernel<<<1, 512>>>();
    scan_final_kernel<<<SCAN_NB, 256>>>();
    scatter_kernel<<<EB, 256>>>(L_rows, L_cols, L_vals);

    // dense projection Xp = X @ W^T (FFMA2)
    transpose_w_kernel<<<(IN_CH * OUT_CH + 255) / 256, 256>>>(W);
    gemm_kernel<<<(N_NODES + 127) / 128, 256>>>(X);

    // atomic-free CSR SpMM (one warp per row)
    csr_spmm_kernel<<<(N_NODES * 32 + 255) / 256, 256>>>(out);
}

// round 11
// speedup vs baseline: 2.8520x; 1.6412x over previous
#include <cuda_runtime.h>
#include <cuda_bf16.h>
#include <cstdint>

#define N_NODES 100000
#define NNZ     1600000
#define IN_CH   256
#define OUT_CH  64

#define SCAN_CHUNK 256
#define SCAN_NB    ((N_NODES + SCAN_CHUNK - 1) / SCAN_CHUNK)   // 391

// ---------------------------------------------------------------------------
// Device scratch (no allocations allowed)
// ---------------------------------------------------------------------------
__device__ float         g_Xp[(size_t)N_NODES * OUT_CH];  // 25.6 MB projected
__device__ __nv_bfloat16 g_Whi[OUT_CH * IN_CH];           // W split hi (bf16)
__device__ __nv_bfloat16 g_Wlo[OUT_CH * IN_CH];           // W split lo (bf16)
__device__ int   g_idx_is32;

__device__ int   g_count[N_NODES];
__device__ int   g_rowptr[N_NODES + 1];
__device__ int   g_cursor[N_NODES];
__device__ int   g_blocksum[SCAN_NB];
__device__ int   g_blockoff[SCAN_NB];
__device__ int2  g_pairs[NNZ];                            // {col, val-bits}

#define SMEM_SWIZZLE_128B(b) ((b) ^ (((b) >> 3) & 0x70))

__device__ __forceinline__ uint32_t smem_u32(const void* p) {
    uint32_t a;
    asm("{ .reg .u64 t; cvta.to.shared.u64 t, %1; cvt.u32.u64 %0, t; }"
        : "=r"(a) : "l"(p));
    return a;
}

#define LDSM_X4(r0, r1, r2, r3, addr) \
    asm volatile("ldmatrix.sync.aligned.m8n8.x4.shared.b16 {%0,%1,%2,%3}, [%4];" \
                 : "=r"(r0), "=r"(r1), "=r"(r2), "=r"(r3) : "r"(addr))

#define LDSM_X2(r0, r1, addr) \
    asm volatile("ldmatrix.sync.aligned.m8n8.x2.shared.b16 {%0,%1}, [%2];" \
                 : "=r"(r0), "=r"(r1) : "r"(addr))

#define MMA_BF16(d0, d1, d2, d3, a0, a1, a2, a3, b0, b1) \
    asm volatile("mma.sync.aligned.m16n8k16.row.col.f32.bf16.bf16.f32 " \
                 "{%0,%1,%2,%3}, {%4,%5,%6,%7}, {%8,%9}, {%0,%1,%2,%3};" \
                 : "+f"(d0), "+f"(d1), "+f"(d2), "+f"(d3) \
                 : "r"(a0), "r"(a1), "r"(a2), "r"(a3), "r"(b0), "r"(b1))

// ===========================================================================
// CSR build + misc kernels (unchanged from R8 — proven at 219.3us)
// ===========================================================================
__global__ void detect_idx_kernel(const unsigned int* __restrict__ rows_u32) {
    __shared__ int s_any;
    if (threadIdx.x == 0) s_any = 0;
    __syncthreads();
    int local = 0;
    for (int i = threadIdx.x; i < 1024; i += blockDim.x)
        if (rows_u32[2 * i + 1] != 0u) local = 1;
    if (local) atomicOr(&s_any, 1);
    __syncthreads();
    if (threadIdx.x == 0) g_idx_is32 = s_any;
}

__global__ void zero_counts_kernel() {
    int i = blockIdx.x * blockDim.x + threadIdx.x;
    if (i < N_NODES) g_count[i] = 0;
}

__device__ __forceinline__ int load_idx(const void* p, int e) {
    if (g_idx_is32)
        return __ldg(reinterpret_cast<const int*>(p) + e);
    return (int)__ldg(reinterpret_cast<const long long*>(p) + e);
}

__global__ void __launch_bounds__(256) count_kernel(const void* __restrict__ rows_p) {
    int e = blockIdx.x * 256 + threadIdx.x;
    if (e >= NNZ) return;
    atomicAdd(&g_count[load_idx(rows_p, e)], 1);
}

__global__ void __launch_bounds__(256) scan_partial_kernel() {
    __shared__ int sh[256];
    int i = blockIdx.x * SCAN_CHUNK + threadIdx.x;
    sh[threadIdx.x] = (i < N_NODES) ? g_count[i] : 0;
    __syncthreads();
#pragma unroll
    for (int off = 128; off > 0; off >>= 1) {
        if (threadIdx.x < off) sh[threadIdx.x] += sh[threadIdx.x + off];
        __syncthreads();
    }
    if (threadIdx.x == 0) g_blocksum[blockIdx.x] = sh[0];
}

__global__ void __launch_bounds__(512) scan_blocksums_kernel() {
    __shared__ int sh[512];
    int t = threadIdx.x;
    int v = (t < SCAN_NB) ? g_blocksum[t] : 0;
    sh[t] = v;
    __syncthreads();
#pragma unroll
    for (int off = 1; off < 512; off <<= 1) {
        int u = (t >= off) ? sh[t - off] : 0;
        __syncthreads();
        sh[t] += u;
        __syncthreads();
    }
    if (t < SCAN_NB) g_blockoff[t] = sh[t] - v;
}

__global__ void __launch_bounds__(256) scan_final_kernel() {
    __shared__ int sh[256];
    int t = threadIdx.x;
    int i = blockIdx.x * SCAN_CHUNK + t;
    int v = (i < N_NODES) ? g_count[i] : 0;
    sh[t] = v;
    __syncthreads();
#pragma unroll
    for (int off = 1; off < 256; off <<= 1) {
        int u = (t >= off) ? sh[t - off] : 0;
        __syncthreads();
        sh[t] += u;
        __syncthreads();
    }
    if (i < N_NODES) {
        int excl = g_blockoff[blockIdx.x] + sh[t] - v;
        g_rowptr[i] = excl;
        g_cursor[i] = excl;
    }
    if (i == 0) g_rowptr[N_NODES] = NNZ;
}

__global__ void __launch_bounds__(256) scatter_kernel(
    const void* __restrict__ rows_p,
    const void* __restrict__ cols_p,
    const float* __restrict__ vals)
{
    int e = blockIdx.x * 256 + threadIdx.x;
    if (e >= NNZ) return;
    int row = load_idx(rows_p, e);
    int col = load_idx(cols_p, e);
    float v = __ldg(vals + e);
    int pos = atomicAdd(&g_cursor[row], 1);
    g_pairs[pos] = make_int2(col, __float_as_int(v));
}

// ---------------------------------------------------------------------------
// Split W into bf16 hi/lo (round-to-nearest hi; lo = residual).
// W [OUT_CH, IN_CH] row-major = the K-major [N, K] layout mma's B wants.
// ---------------------------------------------------------------------------
__global__ void w_split_kernel(const float* __restrict__ W) {
    int i = blockIdx.x * blockDim.x + threadIdx.x;
    if (i < OUT_CH * IN_CH) {
        float w = W[i];
        __nv_bfloat16 hi = __float2bfloat16(w);
        float lof = w - __bfloat162float(hi);
        g_Whi[i] = hi;
        g_Wlo[i] = __float2bfloat16(lof);
    }
}

// ===========================================================================
// Tensor-core GEMM via mma.sync m16n8k16 bf16 (hi/lo split, 3 products).
// CTA = 256 thr (8 warps). Warp w: rows row0 + w*16 .. +15, all 64 outputs.
// K chunked by 64. SW128-swizzled smem tiles, ldmatrix loads.
// ===========================================================================
#define SA_HI 0
#define SA_LO 16384
#define SB_HI 32768
#define SB_LO 40960
#define SMEM_GEMM_TOTAL 49152

__global__ void __launch_bounds__(256)
gemm_mma_kernel(const float* __restrict__ X) {
    extern __shared__ char smem[];
    const uint32_t sbase = smem_u32(smem);
    const int tid  = threadIdx.x;
    const int w    = tid >> 5;
    const int lane = tid & 31;
    const int row0 = blockIdx.x * 128;

    // D accumulators: 8 n-tiles x 4 fp32
    float d[8][4];
#pragma unroll
    for (int j = 0; j < 8; j++)
#pragma unroll
        for (int k = 0; k < 4; k++) d[j][k] = 0.f;

    // ldmatrix address components (constant across chunks)
    const uint32_t a_row  = (uint32_t)(w * 16 + (lane & 15));
    const uint32_t a_colb = (uint32_t)((lane >> 4) * 16);
    const int tt = lane & 15;
    const uint32_t b_row  = (uint32_t)(tt & 7);           // within n-tile
    const uint32_t b_half = (uint32_t)((tt >> 3) * 16);

    for (int c = 0; c < 4; c++) {
        const int kc = c * 64;

        // ---- A fill: 128 rows x 64 k, fp32 -> bf16 trunc-hi + rn-lo ----
#pragma unroll
        for (int i = 0; i < 8; i++) {
            int slot = tid + i * 256;        // 0..2047
            int q = slot & 15;               // float4 within 64-float row
            int r = slot >> 4;               // row 0..127
            int grow = row0 + r;
            if (grow >= N_NODES) grow = N_NODES - 1;   // clamp dup (not stored)
            float4 v = *reinterpret_cast<const float4*>(
                X + (size_t)grow * IN_CH + kc + q * 4);

            uint32_t xb = __float_as_uint(v.x), yb = __float_as_uint(v.y);
            uint32_t zb = __float_as_uint(v.z), wb = __float_as_uint(v.w);
            uint32_t hp0, hp1;
            asm("prmt.b32 %0, %1, %2, 0x7632;" : "=r"(hp0) : "r"(xb), "r"(yb));
            asm("prmt.b32 %0, %1, %2, 0x7632;" : "=r"(hp1) : "r"(zb), "r"(wb));
            float lx = v.x - __uint_as_float(xb & 0xFFFF0000u);
            float ly = v.y - __uint_as_float(yb & 0xFFFF0000u);
            float lz = v.z - __uint_as_float(zb & 0xFFFF0000u);
            float lw = v.w - __uint_as_float(wb & 0xFFFF0000u);
            uint32_t lp0, lp1;
            asm("cvt.rn.bf16x2.f32 %0, %1, %2;" : "=r"(lp0) : "f"(ly), "f"(lx));
            asm("cvt.rn.bf16x2.f32 %0, %1, %2;" : "=r"(lp1) : "f"(lw), "f"(lz));

            uint32_t off = SMEM_SWIZZLE_128B((uint32_t)(r * 128 + q * 8));
            *reinterpret_cast<uint2*>(smem + SA_HI + off) = make_uint2(hp0, hp1);
            *reinterpret_cast<uint2*>(smem + SA_LO + off) = make_uint2(lp0, lp1);
        }
        // ---- B fill: 64 n x 64 k from pre-split g_Whi / g_Wlo ----
#pragma unroll
        for (int i = 0; i < 4; i++) {
            int slot = tid + i * 256;        // 0..1023
            int q = slot & 15;
            int n = slot >> 4;               // 0..63
            uint2 vh = *reinterpret_cast<const uint2*>(g_Whi + n * IN_CH + kc + q * 4);
            uint2 vl = *reinterpret_cast<const uint2*>(g_Wlo + n * IN_CH + kc + q * 4);
            uint32_t off = SMEM_SWIZZLE_128B((uint32_t)(n * 128 + q * 8));
            *reinterpret_cast<uint2*>(smem + SB_HI + off) = vh;
            *reinterpret_cast<uint2*>(smem + SB_LO + off) = vl;
        }
        __syncthreads();

        // ---- compute: 4 k16 steps, 8 n-tiles, 3 products each ----
#pragma unroll
        for (int ks = 0; ks < 4; ks++) {
            uint32_t abyte = SMEM_SWIZZLE_128B(a_row * 128 + (uint32_t)(ks * 32) + a_colb);
            uint32_t ah0, ah1, ah2, ah3, al0, al1, al2, al3;
            LDSM_X4(ah0, ah1, ah2, ah3, sbase + SA_HI + abyte);
            LDSM_X4(al0, al1, al2, al3, sbase + SA_LO + abyte);
#pragma unroll
            for (int j = 0; j < 8; j++) {
                uint32_t bbyte = SMEM_SWIZZLE_128B(
                    (uint32_t)(j * 8 + b_row) * 128 + (uint32_t)(ks * 32) + b_half);
                uint32_t bh0, bh1, bl0, bl1;
                LDSM_X2(bh0, bh1, sbase + SB_HI + bbyte);
                LDSM_X2(bl0, bl1, sbase + SB_LO + bbyte);
                MMA_BF16(d[j][0], d[j][1], d[j][2], d[j][3],
                         ah0, ah1, ah2, ah3, bh0, bh1);
                MMA_BF16(d[j][0], d[j][1], d[j][2], d[j][3],
                         ah0, ah1, ah2, ah3, bl0, bl1);
                MMA_BF16(d[j][0], d[j][1], d[j][2], d[j][3],
                         al0, al1, al2, al3, bh0, bh1);
            }
        }
        __syncthreads();
    }

    // ---- epilogue: d[j]{0,1} -> row t/4, cols j*8+(t%4)*2; {2,3} -> row+8
    int r_lo = row0 + w * 16 + (lane >> 2);
    int r_hi = r_lo + 8;
    int cbase = (lane & 3) * 2;
#pragma unroll
    for (int j = 0; j < 8; j++) {
        int col = j * 8 + cbase;
        if (r_lo < N_NODES)
            *reinterpret_cast<float2*>(g_Xp + (size_t)r_lo * OUT_CH + col)
                = make_float2(d[j][0], d[j][1]);
        if (r_hi < N_NODES)
            *reinterpret_cast<float2*>(g_Xp + (size_t)r_hi * OUT_CH + col)
                = make_float2(d[j][2], d[j][3]);
    }
}

// ---------------------------------------------------------------------------
// CSR SpMM: one warp per output row, no atomics. (unchanged from R8)
// ---------------------------------------------------------------------------
__global__ void __launch_bounds__(256) csr_spmm_kernel(float* __restrict__ out) {
    int w = (blockIdx.x * 256 + threadIdx.x) >> 5;
    if (w >= N_NODES) return;
    int lane = threadIdx.x & 31;

    int s = __ldg(&g_rowptr[w]);
    int e = __ldg(&g_rowptr[w + 1]);

    const float2* Xp2 = reinterpret_cast<const float2*>(g_Xp);
    float2 acc = make_float2(0.f, 0.f);

    int i = s;
    for (; i + 4 <= e; i += 4) {
        int2 p0 = __ldg(&g_pairs[i + 0]);
        int2 p1 = __ldg(&g_pairs[i + 1]);
        int2 p2 = __ldg(&g_pairs[i + 2]);
        int2 p3 = __ldg(&g_pairs[i + 3]);
        float2 x0 = __ldg(Xp2 + (size_t)p0.x * 32 + lane);
        float2 x1 = __ldg(Xp2 + (size_t)p1.x * 32 + lane);
        float2 x2 = __ldg(Xp2 + (size_t)p2.x * 32 + lane);
        float2 x3 = __ldg(Xp2 + (size_t)p3.x * 32 + lane);
        float v0 = __int_as_float(p0.y), v1 = __int_as_float(p1.y);
        float v2 = __int_as_float(p2.y), v3 = __int_as_float(p3.y);
        acc.x += v0 * x0.x; acc.y += v0 * x0.y;
        acc.x += v1 * x1.x; acc.y += v1 * x1.y;
        acc.x += v2 * x2.x; acc.y += v2 * x2.y;
        acc.x += v3 * x3.x; acc.y += v3 * x3.y;
    }
    for (; i < e; i++) {
        int2 pr = __ldg(&g_pairs[i]);
        float2 x = __ldg(Xp2 + (size_t)pr.x * 32 + lane);
        float v = __int_as_float(pr.y);
        acc.x += v * x.x; acc.y += v * x.y;
    }

    reinterpret_cast<float2*>(out)[(size_t)w * 32 + lane] = acc;
}

// ---------------------------------------------------------------------------
// kernel_launch
// Inputs (metadata order): g1, g2, X, W_lin, L_rows, L_cols, L_vals
// ---------------------------------------------------------------------------
extern "C" void kernel_launch(void* const* d_in, const int* in_sizes, int n_in,
                              void* d_out, int out_size) {
    int base = n_in - 5;
    const float* X      = reinterpret_cast<const float*>(d_in[base + 0]);
    const float* W      = reinterpret_cast<const float*>(d_in[base + 1]);
    const void*  L_rows = d_in[base + 2];
    const void*  L_cols = d_in[base + 3];
    const float* L_vals = reinterpret_cast<const float*>(d_in[base + 4]);
    float* out = reinterpret_cast<float*>(d_out);

    const int EB = (NNZ + 255) / 256;

    cudaFuncSetAttribute(gemm_mma_kernel,
                         cudaFuncAttributeMaxDynamicSharedMemorySize,
                         SMEM_GEMM_TOTAL);

    // index dtype detection + CSR build
    detect_idx_kernel<<<1, 256>>>(reinterpret_cast<const unsigned int*>(L_rows));
    zero_counts_kernel<<<(N_NODES + 255) / 256, 256>>>();
    count_kernel<<<EB, 256>>>(L_rows);
    scan_partial_kernel<<<SCAN_NB, 256>>>();
    scan_blocksums_kernel<<<1, 512>>>();
    scan_final_kernel<<<SCAN_NB, 256>>>();
    scatter_kernel<<<EB, 256>>>(L_rows, L_cols, L_vals);

    // dense projection Xp = X @ W^T on tensor cores (bf16 hi/lo, fp32 accum)
    w_split_kernel<<<(OUT_CH * IN_CH + 255) / 256, 256>>>(W);
    gemm_mma_kernel<<<(N_NODES + 127) / 128, 256, SMEM_GEMM_TOTAL>>>(X);

    // atomic-free CSR SpMM (one warp per row)
    csr_spmm_kernel<<<(N_NODES * 32 + 255) / 256, 256>>>(out);
}

// round 12
// speedup vs baseline: 3.1203x; 1.0941x over previous
#include <cuda_runtime.h>
#include <cuda_bf16.h>
#include <cstdint>

#define N_NODES 100000
#define NNZ     1600000
#define IN_CH   256
#define OUT_CH  64

#define SCAN_CHUNK 256
#define SCAN_NB    ((N_NODES + SCAN_CHUNK - 1) / SCAN_CHUNK)   // 391

// ---------------------------------------------------------------------------
// Device scratch (no allocations allowed)
// ---------------------------------------------------------------------------
__device__ float         g_Xp[(size_t)N_NODES * OUT_CH];  // 25.6 MB projected
__device__ __nv_bfloat16 g_Whi[OUT_CH * IN_CH];           // W split hi (bf16)
__device__ __nv_bfloat16 g_Wlo[OUT_CH * IN_CH];           // W split lo (bf16)
__device__ int   g_idx_is32;

__device__ int   g_count[N_NODES];
__device__ int   g_rowptr[N_NODES + 1];
__device__ int   g_cursor[N_NODES];
__device__ int   g_blocksum[SCAN_NB];
__device__ int   g_blockoff[SCAN_NB];
__device__ int2  g_pairs[NNZ];                            // {col, val-bits}

#define SMEM_SWIZZLE_128B(b) ((b) ^ (((b) >> 3) & 0x70))

__device__ __forceinline__ uint32_t smem_u32(const void* p) {
    uint32_t a;
    asm("{ .reg .u64 t; cvta.to.shared.u64 t, %1; cvt.u32.u64 %0, t; }"
        : "=r"(a) : "l"(p));
    return a;
}

#define LDSM_X4(r0, r1, r2, r3, addr) \
    asm volatile("ldmatrix.sync.aligned.m8n8.x4.shared.b16 {%0,%1,%2,%3}, [%4];" \
                 : "=r"(r0), "=r"(r1), "=r"(r2), "=r"(r3) : "r"(addr))

#define LDSM_X2(r0, r1, addr) \
    asm volatile("ldmatrix.sync.aligned.m8n8.x2.shared.b16 {%0,%1}, [%2];" \
                 : "=r"(r0), "=r"(r1) : "r"(addr))

#define MMA_BF16(d0, d1, d2, d3, a0, a1, a2, a3, b0, b1) \
    asm volatile("mma.sync.aligned.m16n8k16.row.col.f32.bf16.bf16.f32 " \
                 "{%0,%1,%2,%3}, {%4,%5,%6,%7}, {%8,%9}, {%0,%1,%2,%3};" \
                 : "+f"(d0), "+f"(d1), "+f"(d2), "+f"(d3) \
                 : "r"(a0), "r"(a1), "r"(a2), "r"(a3), "r"(b0), "r"(b1))

// ===========================================================================
// CSR build + misc kernels (proven)
// ===========================================================================
__global__ void detect_idx_kernel(const unsigned int* __restrict__ rows_u32) {
    __shared__ int s_any;
    if (threadIdx.x == 0) s_any = 0;
    __syncthreads();
    int local = 0;
    for (int i = threadIdx.x; i < 1024; i += blockDim.x)
        if (rows_u32[2 * i + 1] != 0u) local = 1;
    if (local) atomicOr(&s_any, 1);
    __syncthreads();
    if (threadIdx.x == 0) g_idx_is32 = s_any;
}

__global__ void zero_counts_kernel() {
    int i = blockIdx.x * blockDim.x + threadIdx.x;
    if (i < N_NODES) g_count[i] = 0;
}

__device__ __forceinline__ int load_idx(const void* p, int e) {
    if (g_idx_is32)
        return __ldg(reinterpret_cast<const int*>(p) + e);
    return (int)__ldg(reinterpret_cast<const long long*>(p) + e);
}

__global__ void __launch_bounds__(256) count_kernel(const void* __restrict__ rows_p) {
    int e = blockIdx.x * 256 + threadIdx.x;
    if (e >= NNZ) return;
    atomicAdd(&g_count[load_idx(rows_p, e)], 1);
}

__global__ void __launch_bounds__(256) scan_partial_kernel() {
    __shared__ int sh[256];
    int i = blockIdx.x * SCAN_CHUNK + threadIdx.x;
    sh[threadIdx.x] = (i < N_NODES) ? g_count[i] : 0;
    __syncthreads();
#pragma unroll
    for (int off = 128; off > 0; off >>= 1) {
        if (threadIdx.x < off) sh[threadIdx.x] += sh[threadIdx.x + off];
        __syncthreads();
    }
    if (threadIdx.x == 0) g_blocksum[blockIdx.x] = sh[0];
}

__global__ void __launch_bounds__(512) scan_blocksums_kernel() {
    __shared__ int sh[512];
    int t = threadIdx.x;
    int v = (t < SCAN_NB) ? g_blocksum[t] : 0;
    sh[t] = v;
    __syncthreads();
#pragma unroll
    for (int off = 1; off < 512; off <<= 1) {
        int u = (t >= off) ? sh[t - off] : 0;
        __syncthreads();
        sh[t] += u;
        __syncthreads();
    }
    if (t < SCAN_NB) g_blockoff[t] = sh[t] - v;
}

__global__ void __launch_bounds__(256) scan_final_kernel() {
    __shared__ int sh[256];
    int t = threadIdx.x;
    int i = blockIdx.x * SCAN_CHUNK + t;
    int v = (i < N_NODES) ? g_count[i] : 0;
    sh[t] = v;
    __syncthreads();
#pragma unroll
    for (int off = 1; off < 256; off <<= 1) {
        int u = (t >= off) ? sh[t - off] : 0;
        __syncthreads();
        sh[t] += u;
        __syncthreads();
    }
    if (i < N_NODES) {
        int excl = g_blockoff[blockIdx.x] + sh[t] - v;
        g_rowptr[i] = excl;
        g_cursor[i] = excl;
    }
    if (i == 0) g_rowptr[N_NODES] = NNZ;
}

// 2 edges per thread
__global__ void __launch_bounds__(256) scatter_kernel(
    const void* __restrict__ rows_p,
    const void* __restrict__ cols_p,
    const float* __restrict__ vals)
{
    int t0 = (blockIdx.x * 256 + threadIdx.x) * 2;
#pragma unroll
    for (int j = 0; j < 2; j++) {
        int e = t0 + j;
        if (e >= NNZ) return;
        int row = load_idx(rows_p, e);
        int col = load_idx(cols_p, e);
        float v = __ldg(vals + e);
        int pos = atomicAdd(&g_cursor[row], 1);
        g_pairs[pos] = make_int2(col, __float_as_int(v));
    }
}

// ---------------------------------------------------------------------------
// Split W into bf16 hi/lo. W [OUT_CH, IN_CH] row-major = K-major [N,K] for mma B.
// ---------------------------------------------------------------------------
__global__ void w_split_kernel(const float* __restrict__ W) {
    int i = blockIdx.x * blockDim.x + threadIdx.x;
    if (i < OUT_CH * IN_CH) {
        float w = W[i];
        __nv_bfloat16 hi = __float2bfloat16(w);
        float lof = w - __bfloat162float(hi);
        g_Whi[i] = hi;
        g_Wlo[i] = __float2bfloat16(lof);
    }
}

// ===========================================================================
// Tensor-core GEMM via mma.sync m16n8k16 bf16 (hi/lo split, 3 products).
// (unchanged from R11 — proven at 133.6us total)
// ===========================================================================
#define SA_HI 0
#define SA_LO 16384
#define SB_HI 32768
#define SB_LO 40960
#define SMEM_GEMM_TOTAL 49152

__global__ void __launch_bounds__(256)
gemm_mma_kernel(const float* __restrict__ X) {
    extern __shared__ char smem[];
    const uint32_t sbase = smem_u32(smem);
    const int tid  = threadIdx.x;
    const int w    = tid >> 5;
    const int lane = tid & 31;
    const int row0 = blockIdx.x * 128;

    float d[8][4];
#pragma unroll
    for (int j = 0; j < 8; j++)
#pragma unroll
        for (int k = 0; k < 4; k++) d[j][k] = 0.f;

    const uint32_t a_row  = (uint32_t)(w * 16 + (lane & 15));
    const uint32_t a_colb = (uint32_t)((lane >> 4) * 16);
    const int tt = lane & 15;
    const uint32_t b_row  = (uint32_t)(tt & 7);
    const uint32_t b_half = (uint32_t)((tt >> 3) * 16);

    for (int c = 0; c < 4; c++) {
        const int kc = c * 64;

#pragma unroll
        for (int i = 0; i < 8; i++) {
            int slot = tid + i * 256;
            int q = slot & 15;
            int r = slot >> 4;
            int grow = row0 + r;
            if (grow >= N_NODES) grow = N_NODES - 1;
            float4 v = *reinterpret_cast<const float4*>(
                X + (size_t)grow * IN_CH + kc + q * 4);

            uint32_t xb = __float_as_uint(v.x), yb = __float_as_uint(v.y);
            uint32_t zb = __float_as_uint(v.z), wb = __float_as_uint(v.w);
            uint32_t hp0, hp1;
            asm("prmt.b32 %0, %1, %2, 0x7632;" : "=r"(hp0) : "r"(xb), "r"(yb));
            asm("prmt.b32 %0, %1, %2, 0x7632;" : "=r"(hp1) : "r"(zb), "r"(wb));
            float lx = v.x - __uint_as_float(xb & 0xFFFF0000u);
            float ly = v.y - __uint_as_float(yb & 0xFFFF0000u);
            float lz = v.z - __uint_as_float(zb & 0xFFFF0000u);
            float lw = v.w - __uint_as_float(wb & 0xFFFF0000u);
            uint32_t lp0, lp1;
            asm("cvt.rn.bf16x2.f32 %0, %1, %2;" : "=r"(lp0) : "f"(ly), "f"(lx));
            asm("cvt.rn.bf16x2.f32 %0, %1, %2;" : "=r"(lp1) : "f"(lw), "f"(lz));

            uint32_t off = SMEM_SWIZZLE_128B((uint32_t)(r * 128 + q * 8));
            *reinterpret_cast<uint2*>(smem + SA_HI + off) = make_uint2(hp0, hp1);
            *reinterpret_cast<uint2*>(smem + SA_LO + off) = make_uint2(lp0, lp1);
        }
#pragma unroll
        for (int i = 0; i < 4; i++) {
            int slot = tid + i * 256;
            int q = slot & 15;
            int n = slot >> 4;
            uint2 vh = *reinterpret_cast<const uint2*>(g_Whi + n * IN_CH + kc + q * 4);
            uint2 vl = *reinterpret_cast<const uint2*>(g_Wlo + n * IN_CH + kc + q * 4);
            uint32_t off = SMEM_SWIZZLE_128B((uint32_t)(n * 128 + q * 8));
            *reinterpret_cast<uint2*>(smem + SB_HI + off) = vh;
            *reinterpret_cast<uint2*>(smem + SB_LO + off) = vl;
        }
        __syncthreads();

#pragma unroll
        for (int ks = 0; ks < 4; ks++) {
            uint32_t abyte = SMEM_SWIZZLE_128B(a_row * 128 + (uint32_t)(ks * 32) + a_colb);
            uint32_t ah0, ah1, ah2, ah3, al0, al1, al2, al3;
            LDSM_X4(ah0, ah1, ah2, ah3, sbase + SA_HI + abyte);
            LDSM_X4(al0, al1, al2, al3, sbase + SA_LO + abyte);
#pragma unroll
            for (int j = 0; j < 8; j++) {
                uint32_t bbyte = SMEM_SWIZZLE_128B(
                    (uint32_t)(j * 8 + b_row) * 128 + (uint32_t)(ks * 32) + b_half);
                uint32_t bh0, bh1, bl0, bl1;
                LDSM_X2(bh0, bh1, sbase + SB_HI + bbyte);
                LDSM_X2(bl0, bl1, sbase + SB_LO + bbyte);
                MMA_BF16(d[j][0], d[j][1], d[j][2], d[j][3],
                         ah0, ah1, ah2, ah3, bh0, bh1);
                MMA_BF16(d[j][0], d[j][1], d[j][2], d[j][3],
                         ah0, ah1, ah2, ah3, bl0, bl1);
                MMA_BF16(d[j][0], d[j][1], d[j][2], d[j][3],
                         al0, al1, al2, al3, bh0, bh1);
            }
        }
        __syncthreads();
    }

    int r_lo = row0 + w * 16 + (lane >> 2);
    int r_hi = r_lo + 8;
    int cbase = (lane & 3) * 2;
#pragma unroll
    for (int j = 0; j < 8; j++) {
        int col = j * 8 + cbase;
        if (r_lo < N_NODES)
            *reinterpret_cast<float2*>(g_Xp + (size_t)r_lo * OUT_CH + col)
                = make_float2(d[j][0], d[j][1]);
        if (r_hi < N_NODES)
            *reinterpret_cast<float2*>(g_Xp + (size_t)r_hi * OUT_CH + col)
                = make_float2(d[j][2], d[j][3]);
    }
}

// ---------------------------------------------------------------------------
// CSR SpMM: one warp per output row, no atomics. (unchanged)
// ---------------------------------------------------------------------------
__global__ void __launch_bounds__(256) csr_spmm_kernel(float* __restrict__ out) {
    int w = (blockIdx.x * 256 + threadIdx.x) >> 5;
    if (w >= N_NODES) return;
    int lane = threadIdx.x & 31;

    int s = __ldg(&g_rowptr[w]);
    int e = __ldg(&g_rowptr[w + 1]);

    const float2* Xp2 = reinterpret_cast<const float2*>(g_Xp);
    float2 acc = make_float2(0.f, 0.f);

    int i = s;
    for (; i + 4 <= e; i += 4) {
        int2 p0 = __ldg(&g_pairs[i + 0]);
        int2 p1 = __ldg(&g_pairs[i + 1]);
        int2 p2 = __ldg(&g_pairs[i + 2]);
        int2 p3 = __ldg(&g_pairs[i + 3]);
        float2 x0 = __ldg(Xp2 + (size_t)p0.x * 32 + lane);
        float2 x1 = __ldg(Xp2 + (size_t)p1.x * 32 + lane);
        float2 x2 = __ldg(Xp2 + (size_t)p2.x * 32 + lane);
        float2 x3 = __ldg(Xp2 + (size_t)p3.x * 32 + lane);
        float v0 = __int_as_float(p0.y), v1 = __int_as_float(p1.y);
        float v2 = __int_as_float(p2.y), v3 = __int_as_float(p3.y);
        acc.x += v0 * x0.x; acc.y += v0 * x0.y;
        acc.x += v1 * x1.x; acc.y += v1 * x1.y;
        acc.x += v2 * x2.x; acc.y += v2 * x2.y;
        acc.x += v3 * x3.x; acc.y += v3 * x3.y;
    }
    for (; i < e; i++) {
        int2 pr = __ldg(&g_pairs[i]);
        float2 x = __ldg(Xp2 + (size_t)pr.x * 32 + lane);
        float v = __int_as_float(pr.y);
        acc.x += v * x.x; acc.y += v * x.y;
    }

    reinterpret_cast<float2*>(out)[(size_t)w * 32 + lane] = acc;
}

// ---------------------------------------------------------------------------
// kernel_launch — fork-join capture: CSR build on the main stream, GEMM on a
// secondary stream, join before the SpMM. Stream/events created lazily on the
// first (correctness) call; during capture only record/wait execute, which
// become graph dependencies.
// Inputs (metadata order): g1, g2, X, W_lin, L_rows, L_cols, L_vals
// ---------------------------------------------------------------------------
extern "C" void kernel_launch(void* const* d_in, const int* in_sizes, int n_in,
                              void* d_out, int out_size) {
    int base = n_in - 5;
    const float* X      = reinterpret_cast<const float*>(d_in[base + 0]);
    const float* W      = reinterpret_cast<const float*>(d_in[base + 1]);
    const void*  L_rows = d_in[base + 2];
    const void*  L_cols = d_in[base + 3];
    const float* L_vals = reinterpret_cast<const float*>(d_in[base + 4]);
    float* out = reinterpret_cast<float*>(d_out);

    const int EB = (NNZ + 255) / 256;

    static cudaStream_t s2 = nullptr;
    static cudaEvent_t ev_fork = nullptr, ev_join = nullptr;
    if (s2 == nullptr) {
        cudaStreamCreateWithFlags(&s2, cudaStreamNonBlocking);
        cudaEventCreateWithFlags(&ev_fork, cudaEventDisableTiming);
        cudaEventCreateWithFlags(&ev_join, cudaEventDisableTiming);
        cudaFuncSetAttribute(gemm_mma_kernel,
                             cudaFuncAttributeMaxDynamicSharedMemorySize,
                             SMEM_GEMM_TOTAL);
    }

    // ---- fork: GEMM pipeline on s2, CSR build on main stream ----
    cudaEventRecord(ev_fork, 0);
    cudaStreamWaitEvent(s2, ev_fork, 0);

    // s2: W split + tensor-core projection
    w_split_kernel<<<(OUT_CH * IN_CH + 255) / 256, 256, 0, s2>>>(W);
    gemm_mma_kernel<<<(N_NODES + 127) / 128, 256, SMEM_GEMM_TOTAL, s2>>>(X);
    cudaEventRecord(ev_join, s2);

    // main stream: index dtype detection + CSR build
    detect_idx_kernel<<<1, 256>>>(reinterpret_cast<const unsigned int*>(L_rows));
    zero_counts_kernel<<<(N_NODES + 255) / 256, 256>>>();
    count_kernel<<<EB, 256>>>(L_rows);
    scan_partial_kernel<<<SCAN_NB, 256>>>();
    scan_blocksums_kernel<<<1, 512>>>();
    scan_final_kernel<<<SCAN_NB, 256>>>();
    scatter_kernel<<<(NNZ / 2 + 255) / 256, 256>>>(L_rows, L_cols, L_vals);

    // ---- join: SpMM needs both g_pairs/g_rowptr and g_Xp ----
    cudaStreamWaitEvent(0, ev_join, 0);
    csr_spmm_kernel<<<(N_NODES * 32 + 255) / 256, 256>>>(out);
}

// round 13
// speedup vs baseline: 3.2533x; 1.0426x over previous
#include <cuda_runtime.h>
#include <cuda_bf16.h>
#include <cstdint>

#define N_NODES 100000
#define NNZ     1600000
#define IN_CH   256
#define OUT_CH  64

#define SCAN_CHUNK 256
#define SCAN_NB    ((N_NODES + SCAN_CHUNK - 1) / SCAN_CHUNK)   // 391

// ---------------------------------------------------------------------------
// Device scratch (no allocations allowed)
// ---------------------------------------------------------------------------
__device__ float         g_Xp[(size_t)N_NODES * OUT_CH];  // 25.6 MB projected
__device__ __nv_bfloat16 g_Whi[OUT_CH * IN_CH];           // W split hi (bf16)
__device__ __nv_bfloat16 g_Wlo[OUT_CH * IN_CH];           // W split lo (bf16)
__device__ int   g_idx_is32;

__device__ int   g_count[N_NODES];
__device__ int   g_rowptr[N_NODES + 1];
__device__ int   g_cursor[N_NODES];
__device__ int   g_blocksum[SCAN_NB];
__device__ int   g_blockoff[SCAN_NB];
__device__ int2  g_pairs[NNZ];                            // {col, val-bits}

#define SMEM_SWIZZLE_128B(b) ((b) ^ (((b) >> 3) & 0x70))

__device__ __forceinline__ uint32_t smem_u32(const void* p) {
    uint32_t a;
    asm("{ .reg .u64 t; cvta.to.shared.u64 t, %1; cvt.u32.u64 %0, t; }"
        : "=r"(a) : "l"(p));
    return a;
}

#define LDSM_X4(r0, r1, r2, r3, addr) \
    asm volatile("ldmatrix.sync.aligned.m8n8.x4.shared.b16 {%0,%1,%2,%3}, [%4];" \
                 : "=r"(r0), "=r"(r1), "=r"(r2), "=r"(r3) : "r"(addr))

#define LDSM_X2(r0, r1, addr) \
    asm volatile("ldmatrix.sync.aligned.m8n8.x2.shared.b16 {%0,%1}, [%2];" \
                 : "=r"(r0), "=r"(r1) : "r"(addr))

#define MMA_BF16(d0, d1, d2, d3, a0, a1, a2, a3, b0, b1) \
    asm volatile("mma.sync.aligned.m16n8k16.row.col.f32.bf16.bf16.f32 " \
                 "{%0,%1,%2,%3}, {%4,%5,%6,%7}, {%8,%9}, {%0,%1,%2,%3};" \
                 : "+f"(d0), "+f"(d1), "+f"(d2), "+f"(d3) \
                 : "r"(a0), "r"(a1), "r"(a2), "r"(a3), "r"(b0), "r"(b1))

// ===========================================================================
// CSR build
// ===========================================================================

// Merged: zero counters everywhere; block 0 additionally detects idx dtype.
__global__ void init_kernel(const unsigned int* __restrict__ rows_u32) {
    int i = blockIdx.x * blockDim.x + threadIdx.x;
    if (i < N_NODES) g_count[i] = 0;
    if (blockIdx.x == 0) {
        __shared__ int s_any;
        if (threadIdx.x == 0) s_any = 0;
        __syncthreads();
        int local = 0;
        for (int j = threadIdx.x; j < 1024; j += blockDim.x)
            if (rows_u32[2 * j + 1] != 0u) local = 1;
        if (local) atomicOr(&s_any, 1);
        __syncthreads();
        if (threadIdx.x == 0) g_idx_is32 = s_any;
    }
}

__device__ __forceinline__ int load_idx(const void* p, int e) {
    if (g_idx_is32)
        return __ldg(reinterpret_cast<const int*>(p) + e);
    return (int)__ldg(reinterpret_cast<const long long*>(p) + e);
}

// 2 edges per thread, vectorized index load
__global__ void __launch_bounds__(256) count_kernel(const void* __restrict__ rows_p) {
    int e0 = (blockIdx.x * 256 + threadIdx.x) * 2;
    if (e0 >= NNZ) return;
    int r0, r1;
    if (g_idx_is32) {
        int2 v = __ldg(reinterpret_cast<const int2*>(rows_p) + (e0 >> 1));
        r0 = v.x; r1 = v.y;
    } else {
        longlong2 v = __ldg(reinterpret_cast<const longlong2*>(rows_p) + (e0 >> 1));
        r0 = (int)v.x; r1 = (int)v.y;
    }
    atomicAdd(&g_count[r0], 1);
    if (e0 + 1 < NNZ) atomicAdd(&g_count[r1], 1);
}

__global__ void __launch_bounds__(256) scan_partial_kernel() {
    __shared__ int sh[256];
    int i = blockIdx.x * SCAN_CHUNK + threadIdx.x;
    sh[threadIdx.x] = (i < N_NODES) ? g_count[i] : 0;
    __syncthreads();
#pragma unroll
    for (int off = 128; off > 0; off >>= 1) {
        if (threadIdx.x < off) sh[threadIdx.x] += sh[threadIdx.x + off];
        __syncthreads();
    }
    if (threadIdx.x == 0) g_blocksum[blockIdx.x] = sh[0];
}

__global__ void __launch_bounds__(512) scan_blocksums_kernel() {
    __shared__ int sh[512];
    int t = threadIdx.x;
    int v = (t < SCAN_NB) ? g_blocksum[t] : 0;
    sh[t] = v;
    __syncthreads();
#pragma unroll
    for (int off = 1; off < 512; off <<= 1) {
        int u = (t >= off) ? sh[t - off] : 0;
        __syncthreads();
        sh[t] += u;
        __syncthreads();
    }
    if (t < SCAN_NB) g_blockoff[t] = sh[t] - v;
}

__global__ void __launch_bounds__(256) scan_final_kernel() {
    __shared__ int sh[256];
    int t = threadIdx.x;
    int i = blockIdx.x * SCAN_CHUNK + t;
    int v = (i < N_NODES) ? g_count[i] : 0;
    sh[t] = v;
    __syncthreads();
#pragma unroll
    for (int off = 1; off < 256; off <<= 1) {
        int u = (t >= off) ? sh[t - off] : 0;
        __syncthreads();
        sh[t] += u;
        __syncthreads();
    }
    if (i < N_NODES) {
        int excl = g_blockoff[blockIdx.x] + sh[t] - v;
        g_rowptr[i] = excl;
        g_cursor[i] = excl;
    }
    if (i == 0) g_rowptr[N_NODES] = NNZ;
}

// 2 edges per thread
__global__ void __launch_bounds__(256) scatter_kernel(
    const void* __restrict__ rows_p,
    const void* __restrict__ cols_p,
    const float* __restrict__ vals)
{
    int t0 = (blockIdx.x * 256 + threadIdx.x) * 2;
#pragma unroll
    for (int j = 0; j < 2; j++) {
        int e = t0 + j;
        if (e >= NNZ) return;
        int row = load_idx(rows_p, e);
        int col = load_idx(cols_p, e);
        float v = __ldg(vals + e);
        int pos = atomicAdd(&g_cursor[row], 1);
        g_pairs[pos] = make_int2(col, __float_as_int(v));
    }
}

// ---------------------------------------------------------------------------
// Split W into bf16 hi/lo. W [OUT_CH, IN_CH] row-major = K-major [N,K] for mma B.
// ---------------------------------------------------------------------------
__global__ void w_split_kernel(const float* __restrict__ W) {
    int i = blockIdx.x * blockDim.x + threadIdx.x;
    if (i < OUT_CH * IN_CH) {
        float w = W[i];
        __nv_bfloat16 hi = __float2bfloat16(w);
        float lof = w - __bfloat162float(hi);
        g_Whi[i] = hi;
        g_Wlo[i] = __float2bfloat16(lof);
    }
}

// ===========================================================================
// Tensor-core GEMM via mma.sync m16n8k16 bf16 (hi/lo split, 3 products).
// (unchanged — proven)
// ===========================================================================
#define SA_HI 0
#define SA_LO 16384
#define SB_HI 32768
#define SB_LO 40960
#define SMEM_GEMM_TOTAL 49152

__global__ void __launch_bounds__(256)
gemm_mma_kernel(const float* __restrict__ X) {
    extern __shared__ char smem[];
    const uint32_t sbase = smem_u32(smem);
    const int tid  = threadIdx.x;
    const int w    = tid >> 5;
    const int lane = tid & 31;
    const int row0 = blockIdx.x * 128;

    float d[8][4];
#pragma unroll
    for (int j = 0; j < 8; j++)
#pragma unroll
        for (int k = 0; k < 4; k++) d[j][k] = 0.f;

    const uint32_t a_row  = (uint32_t)(w * 16 + (lane & 15));
    const uint32_t a_colb = (uint32_t)((lane >> 4) * 16);
    const int tt = lane & 15;
    const uint32_t b_row  = (uint32_t)(tt & 7);
    const uint32_t b_half = (uint32_t)((tt >> 3) * 16);

    for (int c = 0; c < 4; c++) {
        const int kc = c * 64;

#pragma unroll
        for (int i = 0; i < 8; i++) {
            int slot = tid + i * 256;
            int q = slot & 15;
            int r = slot >> 4;
            int grow = row0 + r;
            if (grow >= N_NODES) grow = N_NODES - 1;
            float4 v = *reinterpret_cast<const float4*>(
                X + (size_t)grow * IN_CH + kc + q * 4);

            uint32_t xb = __float_as_uint(v.x), yb = __float_as_uint(v.y);
            uint32_t zb = __float_as_uint(v.z), wb = __float_as_uint(v.w);
            uint32_t hp0, hp1;
            asm("prmt.b32 %0, %1, %2, 0x7632;" : "=r"(hp0) : "r"(xb), "r"(yb));
            asm("prmt.b32 %0, %1, %2, 0x7632;" : "=r"(hp1) : "r"(zb), "r"(wb));
            float lx = v.x - __uint_as_float(xb & 0xFFFF0000u);
            float ly = v.y - __uint_as_float(yb & 0xFFFF0000u);
            float lz = v.z - __uint_as_float(zb & 0xFFFF0000u);
            float lw = v.w - __uint_as_float(wb & 0xFFFF0000u);
            uint32_t lp0, lp1;
            asm("cvt.rn.bf16x2.f32 %0, %1, %2;" : "=r"(lp0) : "f"(ly), "f"(lx));
            asm("cvt.rn.bf16x2.f32 %0, %1, %2;" : "=r"(lp1) : "f"(lw), "f"(lz));

            uint32_t off = SMEM_SWIZZLE_128B((uint32_t)(r * 128 + q * 8));
            *reinterpret_cast<uint2*>(smem + SA_HI + off) = make_uint2(hp0, hp1);
            *reinterpret_cast<uint2*>(smem + SA_LO + off) = make_uint2(lp0, lp1);
        }
#pragma unroll
        for (int i = 0; i < 4; i++) {
            int slot = tid + i * 256;
            int q = slot & 15;
            int n = slot >> 4;
            uint2 vh = *reinterpret_cast<const uint2*>(g_Whi + n * IN_CH + kc + q * 4);
            uint2 vl = *reinterpret_cast<const uint2*>(g_Wlo + n * IN_CH + kc + q * 4);
            uint32_t off = SMEM_SWIZZLE_128B((uint32_t)(n * 128 + q * 8));
            *reinterpret_cast<uint2*>(smem + SB_HI + off) = vh;
            *reinterpret_cast<uint2*>(smem + SB_LO + off) = vl;
        }
        __syncthreads();

#pragma unroll
        for (int ks = 0; ks < 4; ks++) {
            uint32_t abyte = SMEM_SWIZZLE_128B(a_row * 128 + (uint32_t)(ks * 32) + a_colb);
            uint32_t ah0, ah1, ah2, ah3, al0, al1, al2, al3;
            LDSM_X4(ah0, ah1, ah2, ah3, sbase + SA_HI + abyte);
            LDSM_X4(al0, al1, al2, al3, sbase + SA_LO + abyte);
#pragma unroll
            for (int j = 0; j < 8; j++) {
                uint32_t bbyte = SMEM_SWIZZLE_128B(
                    (uint32_t)(j * 8 + b_row) * 128 + (uint32_t)(ks * 32) + b_half);
                uint32_t bh0, bh1, bl0, bl1;
                LDSM_X2(bh0, bh1, sbase + SB_HI + bbyte);
                LDSM_X2(bl0, bl1, sbase + SB_LO + bbyte);
                MMA_BF16(d[j][0], d[j][1], d[j][2], d[j][3],
                         ah0, ah1, ah2, ah3, bh0, bh1);
                MMA_BF16(d[j][0], d[j][1], d[j][2], d[j][3],
                         ah0, ah1, ah2, ah3, bl0, bl1);
                MMA_BF16(d[j][0], d[j][1], d[j][2], d[j][3],
                         al0, al1, al2, al3, bh0, bh1);
            }
        }
        __syncthreads();
    }

    int r_lo = row0 + w * 16 + (lane >> 2);
    int r_hi = r_lo + 8;
    int cbase = (lane & 3) * 2;
#pragma unroll
    for (int j = 0; j < 8; j++) {
        int col = j * 8 + cbase;
        if (r_lo < N_NODES)
            *reinterpret_cast<float2*>(g_Xp + (size_t)r_lo * OUT_CH + col)
                = make_float2(d[j][0], d[j][1]);
        if (r_hi < N_NODES)
            *reinterpret_cast<float2*>(g_Xp + (size_t)r_hi * OUT_CH + col)
                = make_float2(d[j][2], d[j][3]);
    }
}

// ---------------------------------------------------------------------------
// CSR SpMM: HALF-WARP per output row, lane handles 4 channels (float4).
// One LDG.128 warp-instruction now serves two edges (one per half-warp),
// halving LSU issue vs the float2/full-warp version. No atomics.
// ---------------------------------------------------------------------------
__global__ void __launch_bounds__(256) csr_spmm_kernel(float* __restrict__ out) {
    int row = (blockIdx.x * 256 + threadIdx.x) >> 4;   // half-warp -> row
    if (row >= N_NODES) return;
    int l16 = threadIdx.x & 15;

    int s = __ldg(&g_rowptr[row]);
    int e = __ldg(&g_rowptr[row + 1]);

    const float4* Xp4 = reinterpret_cast<const float4*>(g_Xp);
    float4 acc = make_float4(0.f, 0.f, 0.f, 0.f);

    int i = s;
    for (; i + 4 <= e; i += 4) {
        int2 p0 = __ldg(&g_pairs[i + 0]);
        int2 p1 = __ldg(&g_pairs[i + 1]);
        int2 p2 = __ldg(&g_pairs[i + 2]);
        int2 p3 = __ldg(&g_pairs[i + 3]);
        float4 x0 = __ldg(Xp4 + (size_t)p0.x * 16 + l16);
        float4 x1 = __ldg(Xp4 + (size_t)p1.x * 16 + l16);
        float4 x2 = __ldg(Xp4 + (size_t)p2.x * 16 + l16);
        float4 x3 = __ldg(Xp4 + (size_t)p3.x * 16 + l16);
        float v0 = __int_as_float(p0.y), v1 = __int_as_float(p1.y);
        float v2 = __int_as_float(p2.y), v3 = __int_as_float(p3.y);
        acc.x += v0 * x0.x; acc.y += v0 * x0.y; acc.z += v0 * x0.z; acc.w += v0 * x0.w;
        acc.x += v1 * x1.x; acc.y += v1 * x1.y; acc.z += v1 * x1.z; acc.w += v1 * x1.w;
        acc.x += v2 * x2.x; acc.y += v2 * x2.y; acc.z += v2 * x2.z; acc.w += v2 * x2.w;
        acc.x += v3 * x3.x; acc.y += v3 * x3.y; acc.z += v3 * x3.z; acc.w += v3 * x3.w;
    }
    for (; i < e; i++) {
        int2 pr = __ldg(&g_pairs[i]);
        float4 x = __ldg(Xp4 + (size_t)pr.x * 16 + l16);
        float v = __int_as_float(pr.y);
        acc.x += v * x.x; acc.y += v * x.y; acc.z += v * x.z; acc.w += v * x.w;
    }

    reinterpret_cast<float4*>(out)[(size_t)row * 16 + l16] = acc;
}

// ---------------------------------------------------------------------------
// kernel_launch — fork-join capture (proven): CSR build on main stream, GEMM
// on a secondary stream, join before SpMM.
// Inputs (metadata order): g1, g2, X, W_lin, L_rows, L_cols, L_vals
// ---------------------------------------------------------------------------
extern "C" void kernel_launch(void* const* d_in, const int* in_sizes, int n_in,
                              void* d_out, int out_size) {
    int base = n_in - 5;
    const float* X      = reinterpret_cast<const float*>(d_in[base + 0]);
    const float* W      = reinterpret_cast<const float*>(d_in[base + 1]);
    const void*  L_rows = d_in[base + 2];
    const void*  L_cols = d_in[base + 3];
    const float* L_vals = reinterpret_cast<const float*>(d_in[base + 4]);
    float* out = reinterpret_cast<float*>(d_out);

    static cudaStream_t s2 = nullptr;
    static cudaEvent_t ev_fork = nullptr, ev_join = nullptr;
    if (s2 == nullptr) {
        cudaStreamCreateWithFlags(&s2, cudaStreamNonBlocking);
        cudaEventCreateWithFlags(&ev_fork, cudaEventDisableTiming);
        cudaEventCreateWithFlags(&ev_join, cudaEventDisableTiming);
        cudaFuncSetAttribute(gemm_mma_kernel,
                             cudaFuncAttributeMaxDynamicSharedMemorySize,
                             SMEM_GEMM_TOTAL);
    }

    // ---- fork: GEMM pipeline on s2, CSR build on main stream ----
    cudaEventRecord(ev_fork, 0);
    cudaStreamWaitEvent(s2, ev_fork, 0);

    // s2: W split + tensor-core projection
    w_split_kernel<<<(OUT_CH * IN_CH + 255) / 256, 256, 0, s2>>>(W);
    gemm_mma_kernel<<<(N_NODES + 127) / 128, 256, SMEM_GEMM_TOTAL, s2>>>(X);
    cudaEventRecord(ev_join, s2);

    // main stream: zero+detect, count, scan, scatter
    init_kernel<<<(N_NODES + 255) / 256, 256>>>(
        reinterpret_cast<const unsigned int*>(L_rows));
    count_kernel<<<(NNZ / 2 + 255) / 256, 256>>>(L_rows);
    scan_partial_kernel<<<SCAN_NB, 256>>>();
    scan_blocksums_kernel<<<1, 512>>>();
    scan_final_kernel<<<SCAN_NB, 256>>>();
    scatter_kernel<<<(NNZ / 2 + 255) / 256, 256>>>(L_rows, L_cols, L_vals);

    // ---- join: SpMM needs both g_pairs/g_rowptr and g_Xp ----
    cudaStreamWaitEvent(0, ev_join, 0);
    csr_spmm_kernel<<<(N_NODES * 16 + 255) / 256, 256>>>(out);
}

// round 14
// speedup vs baseline: 3.5395x; 1.0880x over previous
#include <cuda_runtime.h>
#include <cuda_bf16.h>
#include <cuda_fp16.h>
#include <cstdint>

#define N_NODES 100000
#define NNZ     1600000
#define IN_CH   256
#define OUT_CH  64

#define SCAN_CHUNK 256
#define SCAN_NB    ((N_NODES + SCAN_CHUNK - 1) / SCAN_CHUNK)   // 391

// ---------------------------------------------------------------------------
// Device scratch (no allocations allowed)
// ---------------------------------------------------------------------------
__device__ __half        g_Xph[(size_t)N_NODES * OUT_CH]; // 12.8 MB projected (fp16)
__device__ __nv_bfloat16 g_Whi[OUT_CH * IN_CH];           // W split hi (bf16)
__device__ __nv_bfloat16 g_Wlo[OUT_CH * IN_CH];           // W split lo (bf16)
__device__ int   g_idx_is32;

__device__ int   g_count[N_NODES];
__device__ int   g_rowptr[N_NODES + 1];
__device__ int   g_rank[NNZ];                             // per-edge rank within row
__device__ int   g_blocksum[SCAN_NB];
__device__ int   g_blockoff[SCAN_NB];
__device__ int2  g_pairs[NNZ];                            // {col, val-bits}

#define SMEM_SWIZZLE_128B(b) ((b) ^ (((b) >> 3) & 0x70))

__device__ __forceinline__ uint32_t smem_u32(const void* p) {
    uint32_t a;
    asm("{ .reg .u64 t; cvta.to.shared.u64 t, %1; cvt.u32.u64 %0, t; }"
        : "=r"(a) : "l"(p));
    return a;
}

#define LDSM_X4(r0, r1, r2, r3, addr) \
    asm volatile("ldmatrix.sync.aligned.m8n8.x4.shared.b16 {%0,%1,%2,%3}, [%4];" \
                 : "=r"(r0), "=r"(r1), "=r"(r2), "=r"(r3) : "r"(addr))

#define LDSM_X2(r0, r1, addr) \
    asm volatile("ldmatrix.sync.aligned.m8n8.x2.shared.b16 {%0,%1}, [%2];" \
                 : "=r"(r0), "=r"(r1) : "r"(addr))

#define MMA_BF16(d0, d1, d2, d3, a0, a1, a2, a3, b0, b1) \
    asm volatile("mma.sync.aligned.m16n8k16.row.col.f32.bf16.bf16.f32 " \
                 "{%0,%1,%2,%3}, {%4,%5,%6,%7}, {%8,%9}, {%0,%1,%2,%3};" \
                 : "+f"(d0), "+f"(d1), "+f"(d2), "+f"(d3) \
                 : "r"(a0), "r"(a1), "r"(a2), "r"(a3), "r"(b0), "r"(b1))

// ===========================================================================
// CSR build
// ===========================================================================

// Merged: zero counters everywhere; block 0 additionally detects idx dtype.
__global__ void init_kernel(const unsigned int* __restrict__ rows_u32) {
    int i = blockIdx.x * blockDim.x + threadIdx.x;
    if (i < N_NODES) g_count[i] = 0;
    if (blockIdx.x == 0) {
        __shared__ int s_any;
        if (threadIdx.x == 0) s_any = 0;
        __syncthreads();
        int local = 0;
        for (int j = threadIdx.x; j < 1024; j += blockDim.x)
            if (rows_u32[2 * j + 1] != 0u) local = 1;
        if (local) atomicOr(&s_any, 1);
        __syncthreads();
        if (threadIdx.x == 0) g_idx_is32 = s_any;
    }
}

__device__ __forceinline__ int load_idx(const void* p, int e) {
    if (g_idx_is32)
        return __ldg(reinterpret_cast<const int*>(p) + e);
    return (int)__ldg(reinterpret_cast<const long long*>(p) + e);
}

// 2 edges per thread, vectorized index load. Records each edge's rank within
// its row so the scatter pass needs no atomics.
__global__ void __launch_bounds__(256) count_kernel(const void* __restrict__ rows_p) {
    int e0 = (blockIdx.x * 256 + threadIdx.x) * 2;
    if (e0 >= NNZ) return;
    int r0, r1;
    if (g_idx_is32) {
        int2 v = __ldg(reinterpret_cast<const int2*>(rows_p) + (e0 >> 1));
        r0 = v.x; r1 = v.y;
    } else {
        longlong2 v = __ldg(reinterpret_cast<const longlong2*>(rows_p) + (e0 >> 1));
        r0 = (int)v.x; r1 = (int)v.y;
    }
    int k0 = atomicAdd(&g_count[r0], 1);
    g_rank[e0] = k0;
    if (e0 + 1 < NNZ) {
        int k1 = atomicAdd(&g_count[r1], 1);
        g_rank[e0 + 1] = k1;
    }
}

__global__ void __launch_bounds__(256) scan_partial_kernel() {
    __shared__ int sh[256];
    int i = blockIdx.x * SCAN_CHUNK + threadIdx.x;
    sh[threadIdx.x] = (i < N_NODES) ? g_count[i] : 0;
    __syncthreads();
#pragma unroll
    for (int off = 128; off > 0; off >>= 1) {
        if (threadIdx.x < off) sh[threadIdx.x] += sh[threadIdx.x + off];
        __syncthreads();
    }
    if (threadIdx.x == 0) g_blocksum[blockIdx.x] = sh[0];
}

__global__ void __launch_bounds__(512) scan_blocksums_kernel() {
    __shared__ int sh[512];
    int t = threadIdx.x;
    int v = (t < SCAN_NB) ? g_blocksum[t] : 0;
    sh[t] = v;
    __syncthreads();
#pragma unroll
    for (int off = 1; off < 512; off <<= 1) {
        int u = (t >= off) ? sh[t - off] : 0;
        __syncthreads();
        sh[t] += u;
        __syncthreads();
    }
    if (t < SCAN_NB) g_blockoff[t] = sh[t] - v;
}

__global__ void __launch_bounds__(256) scan_final_kernel() {
    __shared__ int sh[256];
    int t = threadIdx.x;
    int i = blockIdx.x * SCAN_CHUNK + t;
    int v = (i < N_NODES) ? g_count[i] : 0;
    sh[t] = v;
    __syncthreads();
#pragma unroll
    for (int off = 1; off < 256; off <<= 1) {
        int u = (t >= off) ? sh[t - off] : 0;
        __syncthreads();
        sh[t] += u;
        __syncthreads();
    }
    if (i < N_NODES) g_rowptr[i] = g_blockoff[blockIdx.x] + sh[t] - v;
    if (i == 0) g_rowptr[N_NODES] = NNZ;
}

// Atomic-free scatter: pos = rowptr[row] + rank[e]. 2 edges per thread.
__global__ void __launch_bounds__(256) scatter_kernel(
    const void* __restrict__ rows_p,
    const void* __restrict__ cols_p,
    const float* __restrict__ vals)
{
    int t0 = (blockIdx.x * 256 + threadIdx.x) * 2;
#pragma unroll
    for (int j = 0; j < 2; j++) {
        int e = t0 + j;
        if (e >= NNZ) return;
        int row = load_idx(rows_p, e);
        int col = load_idx(cols_p, e);
        float v = __ldg(vals + e);
        int pos = __ldg(&g_rowptr[row]) + __ldg(&g_rank[e]);
        g_pairs[pos] = make_int2(col, __float_as_int(v));
    }
}

// ---------------------------------------------------------------------------
// Split W into bf16 hi/lo. W [OUT_CH, IN_CH] row-major = K-major [N,K] for mma B.
// ---------------------------------------------------------------------------
__global__ void w_split_kernel(const float* __restrict__ W) {
    int i = blockIdx.x * blockDim.x + threadIdx.x;
    if (i < OUT_CH * IN_CH) {
        float w = W[i];
        __nv_bfloat16 hi = __float2bfloat16(w);
        float lof = w - __bfloat162float(hi);
        g_Whi[i] = hi;
        g_Wlo[i] = __float2bfloat16(lof);
    }
}

// ===========================================================================
// Tensor-core GEMM via mma.sync m16n8k16 bf16 (hi/lo split, 3 products).
// Epilogue now emits fp16 (halves SpMM gather traffic).
// ===========================================================================
#define SA_HI 0
#define SA_LO 16384
#define SB_HI 32768
#define SB_LO 40960
#define SMEM_GEMM_TOTAL 49152

__global__ void __launch_bounds__(256)
gemm_mma_kernel(const float* __restrict__ X) {
    extern __shared__ char smem[];
    const uint32_t sbase = smem_u32(smem);
    const int tid  = threadIdx.x;
    const int w    = tid >> 5;
    const int lane = tid & 31;
    const int row0 = blockIdx.x * 128;

    float d[8][4];
#pragma unroll
    for (int j = 0; j < 8; j++)
#pragma unroll
        for (int k = 0; k < 4; k++) d[j][k] = 0.f;

    const uint32_t a_row  = (uint32_t)(w * 16 + (lane & 15));
    const uint32_t a_colb = (uint32_t)((lane >> 4) * 16);
    const int tt = lane & 15;
    const uint32_t b_row  = (uint32_t)(tt & 7);
    const uint32_t b_half = (uint32_t)((tt >> 3) * 16);

    for (int c = 0; c < 4; c++) {
        const int kc = c * 64;

#pragma unroll
        for (int i = 0; i < 8; i++) {
            int slot = tid + i * 256;
            int q = slot & 15;
            int r = slot >> 4;
            int grow = row0 + r;
            if (grow >= N_NODES) grow = N_NODES - 1;
            float4 v = *reinterpret_cast<const float4*>(
                X + (size_t)grow * IN_CH + kc + q * 4);

            uint32_t xb = __float_as_uint(v.x), yb = __float_as_uint(v.y);
            uint32_t zb = __float_as_uint(v.z), wb = __float_as_uint(v.w);
            uint32_t hp0, hp1;
            asm("prmt.b32 %0, %1, %2, 0x7632;" : "=r"(hp0) : "r"(xb), "r"(yb));
            asm("prmt.b32 %0, %1, %2, 0x7632;" : "=r"(hp1) : "r"(zb), "r"(wb));
            float lx = v.x - __uint_as_float(xb & 0xFFFF0000u);
            float ly = v.y - __uint_as_float(yb & 0xFFFF0000u);
            float lz = v.z - __uint_as_float(zb & 0xFFFF0000u);
            float lw = v.w - __uint_as_float(wb & 0xFFFF0000u);
            uint32_t lp0, lp1;
            asm("cvt.rn.bf16x2.f32 %0, %1, %2;" : "=r"(lp0) : "f"(ly), "f"(lx));
            asm("cvt.rn.bf16x2.f32 %0, %1, %2;" : "=r"(lp1) : "f"(lw), "f"(lz));

            uint32_t off = SMEM_SWIZZLE_128B((uint32_t)(r * 128 + q * 8));
            *reinterpret_cast<uint2*>(smem + SA_HI + off) = make_uint2(hp0, hp1);
            *reinterpret_cast<uint2*>(smem + SA_LO + off) = make_uint2(lp0, lp1);
        }
#pragma unroll
        for (int i = 0; i < 4; i++) {
            int slot = tid + i * 256;
            int q = slot & 15;
            int n = slot >> 4;
            uint2 vh = *reinterpret_cast<const uint2*>(g_Whi + n * IN_CH + kc + q * 4);
            uint2 vl = *reinterpret_cast<const uint2*>(g_Wlo + n * IN_CH + kc + q * 4);
            uint32_t off = SMEM_SWIZZLE_128B((uint32_t)(n * 128 + q * 8));
            *reinterpret_cast<uint2*>(smem + SB_HI + off) = vh;
            *reinterpret_cast<uint2*>(smem + SB_LO + off) = vl;
        }
        __syncthreads();

#pragma unroll
        for (int ks = 0; ks < 4; ks++) {
            uint32_t abyte = SMEM_SWIZZLE_128B(a_row * 128 + (uint32_t)(ks * 32) + a_colb);
            uint32_t ah0, ah1, ah2, ah3, al0, al1, al2, al3;
            LDSM_X4(ah0, ah1, ah2, ah3, sbase + SA_HI + abyte);
            LDSM_X4(al0, al1, al2, al3, sbase + SA_LO + abyte);
#pragma unroll
            for (int j = 0; j < 8; j++) {
                uint32_t bbyte = SMEM_SWIZZLE_128B(
                    (uint32_t)(j * 8 + b_row) * 128 + (uint32_t)(ks * 32) + b_half);
                uint32_t bh0, bh1, bl0, bl1;
                LDSM_X2(bh0, bh1, sbase + SB_HI + bbyte);
                LDSM_X2(bl0, bl1, sbase + SB_LO + bbyte);
                MMA_BF16(d[j][0], d[j][1], d[j][2], d[j][3],
                         ah0, ah1, ah2, ah3, bh0, bh1);
                MMA_BF16(d[j][0], d[j][1], d[j][2], d[j][3],
                         ah0, ah1, ah2, ah3, bl0, bl1);
                MMA_BF16(d[j][0], d[j][1], d[j][2], d[j][3],
                         al0, al1, al2, al3, bh0, bh1);
            }
        }
        __syncthreads();
    }

    // epilogue -> fp16
    int r_lo = row0 + w * 16 + (lane >> 2);
    int r_hi = r_lo + 8;
    int cbase = (lane & 3) * 2;
#pragma unroll
    for (int j = 0; j < 8; j++) {
        int col = j * 8 + cbase;
        if (r_lo < N_NODES)
            *reinterpret_cast<__half2*>(g_Xph + (size_t)r_lo * OUT_CH + col)
                = __floats2half2_rn(d[j][0], d[j][1]);
        if (r_hi < N_NODES)
            *reinterpret_cast<__half2*>(g_Xph + (size_t)r_hi * OUT_CH + col)
                = __floats2half2_rn(d[j][2], d[j][3]);
    }
}

// ---------------------------------------------------------------------------
// CSR SpMM: half-warp per row, lane handles 4 fp16 channels (8B gather).
// fp32 accumulate, fp32 output. No atomics.
// ---------------------------------------------------------------------------
__global__ void __launch_bounds__(256) csr_spmm_kernel(float* __restrict__ out) {
    int row = (blockIdx.x * 256 + threadIdx.x) >> 4;
    if (row >= N_NODES) return;
    int l16 = threadIdx.x & 15;

    int s = __ldg(&g_rowptr[row]);
    int e = __ldg(&g_rowptr[row + 1]);

    const uint2* Xp8 = reinterpret_cast<const uint2*>(g_Xph);  // 8B = 4 halves
    float4 acc = make_float4(0.f, 0.f, 0.f, 0.f);

    int i = s;
    for (; i + 4 <= e; i += 4) {
        int2 p0 = __ldg(&g_pairs[i + 0]);
        int2 p1 = __ldg(&g_pairs[i + 1]);
        int2 p2 = __ldg(&g_pairs[i + 2]);
        int2 p3 = __ldg(&g_pairs[i + 3]);
        uint2 u0 = __ldg(Xp8 + (size_t)p0.x * 16 + l16);
        uint2 u1 = __ldg(Xp8 + (size_t)p1.x * 16 + l16);
        uint2 u2 = __ldg(Xp8 + (size_t)p2.x * 16 + l16);
        uint2 u3 = __ldg(Xp8 + (size_t)p3.x * 16 + l16);
        float v0 = __int_as_float(p0.y), v1 = __int_as_float(p1.y);
        float v2 = __int_as_float(p2.y), v3 = __int_as_float(p3.y);
#define ACC_EDGE(u, v) do {                                                   \
        float2 fa = __half22float2(*reinterpret_cast<const __half2*>(&(u).x));\
        float2 fb = __half22float2(*reinterpret_cast<const __half2*>(&(u).y));\
        acc.x += (v) * fa.x; acc.y += (v) * fa.y;                             \
        acc.z += (v) * fb.x; acc.w += (v) * fb.y; } while (0)
        ACC_EDGE(u0, v0); ACC_EDGE(u1, v1); ACC_EDGE(u2, v2); ACC_EDGE(u3, v3);
    }
    for (; i < e; i++) {
        int2 pr = __ldg(&g_pairs[i]);
        uint2 u = __ldg(Xp8 + (size_t)pr.x * 16 + l16);
        float v = __int_as_float(pr.y);
        ACC_EDGE(u, v);
    }
#undef ACC_EDGE

    reinterpret_cast<float4*>(out)[(size_t)row * 16 + l16] = acc;
}

// ---------------------------------------------------------------------------
// kernel_launch — fork-join capture (proven): CSR build on main stream, GEMM
// on a secondary stream, join before SpMM.
// Inputs (metadata order): g1, g2, X, W_lin, L_rows, L_cols, L_vals
// ---------------------------------------------------------------------------
extern "C" void kernel_launch(void* const* d_in, const int* in_sizes, int n_in,
                              void* d_out, int out_size) {
    int base = n_in - 5;
    const float* X      = reinterpret_cast<const float*>(d_in[base + 0]);
    const float* W      = reinterpret_cast<const float*>(d_in[base + 1]);
    const void*  L_rows = d_in[base + 2];
    const void*  L_cols = d_in[base + 3];
    const float* L_vals = reinterpret_cast<const float*>(d_in[base + 4]);
    float* out = reinterpret_cast<float*>(d_out);

    static cudaStream_t s2 = nullptr;
    static cudaEvent_t ev_fork = nullptr, ev_join = nullptr;
    if (s2 == nullptr) {
        cudaStreamCreateWithFlags(&s2, cudaStreamNonBlocking);
        cudaEventCreateWithFlags(&ev_fork, cudaEventDisableTiming);
        cudaEventCreateWithFlags(&ev_join, cudaEventDisableTiming);
        cudaFuncSetAttribute(gemm_mma_kernel,
                             cudaFuncAttributeMaxDynamicSharedMemorySize,
                             SMEM_GEMM_TOTAL);
    }

    // ---- fork: GEMM pipeline on s2, CSR build on main stream ----
    cudaEventRecord(ev_fork, 0);
    cudaStreamWaitEvent(s2, ev_fork, 0);

    // s2: W split + tensor-core projection (fp16 output)
    w_split_kernel<<<(OUT_CH * IN_CH + 255) / 256, 256, 0, s2>>>(W);
    gemm_mma_kernel<<<(N_NODES + 127) / 128, 256, SMEM_GEMM_TOTAL, s2>>>(X);
    cudaEventRecord(ev_join, s2);

    // main stream: zero+detect, count(+rank), scan, atomic-free scatter
    init_kernel<<<(N_NODES + 255) / 256, 256>>>(
        reinterpret_cast<const unsigned int*>(L_rows));
    count_kernel<<<(NNZ / 2 + 255) / 256, 256>>>(L_rows);
    scan_partial_kernel<<<SCAN_NB, 256>>>();
    scan_blocksums_kernel<<<1, 512>>>();
    scan_final_kernel<<<SCAN_NB, 256>>>();
    scatter_kernel<<<(NNZ / 2 + 255) / 256, 256>>>(L_rows, L_cols, L_vals);

    // ---- join: SpMM needs both g_pairs/g_rowptr and g_Xph ----
    cudaStreamWaitEvent(0, ev_join, 0);
    csr_spmm_kernel<<<(N_NODES * 16 + 255) / 256, 256>>>(out);
}